// round 4
// baseline (speedup 1.0000x reference)
#include <cuda_runtime.h>
#include <math.h>

// ---------------------------------------------------------------------------
// TransformerBlock: B=128, T=256, C=384
//   h = LN1(x); qkv = h@W_attn+b_attn; causal softmax attention (single head,
//   head dim = C); x1 = x + y@W_proj+b_proj; x_out = x1 + relu(LN2(x1)@W1+b1)@W2+b2
// fp32 baseline: templated 128x128x8 register-blocked SGEMM with fused
// epilogue (alpha, bias, relu, residual), batched via blockIdx.z.
// ---------------------------------------------------------------------------

#define BATCH 128
#define SEQ   256
#define EMB   384
#define MROWS (BATCH * SEQ)   // 32768

// Scratch (static device globals — no allocation allowed).
// g_h is reused for: LN1 out -> attn output y -> LN2 out (disjoint lifetimes).
__device__ float g_h  [(size_t)MROWS * EMB];          // 48 MB
__device__ float g_qkv[(size_t)MROWS * 3 * EMB];      // 144 MB
__device__ float g_att[(size_t)BATCH * SEQ * SEQ];    // 33.5 MB
__device__ float g_x1 [(size_t)MROWS * EMB];          // 48 MB
__device__ float g_f  [(size_t)MROWS * 4 * EMB];      // 192 MB

// ---------------------------------------------------------------------------
// LayerNorm: one block per row, 128 threads, 3 elements per thread (C=384).
// ---------------------------------------------------------------------------
__global__ __launch_bounds__(128)
void ln_kernel(const float* __restrict__ x, const float* __restrict__ g,
               const float* __restrict__ b, float* __restrict__ out)
{
    const long row = blockIdx.x;
    const float* xr = x + row * (long)EMB;
    const int tid = threadIdx.x;

    float v0 = xr[tid], v1 = xr[tid + 128], v2 = xr[tid + 256];
    float s = v0 + v1 + v2;
    float q = v0 * v0 + v1 * v1 + v2 * v2;

    __shared__ float ss[4], qq[4];
    const int lane = tid & 31, w = tid >> 5;
#pragma unroll
    for (int o = 16; o; o >>= 1) {
        s += __shfl_down_sync(0xffffffffu, s, o);
        q += __shfl_down_sync(0xffffffffu, q, o);
    }
    if (!lane) { ss[w] = s; qq[w] = q; }
    __syncthreads();
    s = ss[0] + ss[1] + ss[2] + ss[3];
    q = qq[0] + qq[1] + qq[2] + qq[3];

    const float mu  = s * (1.0f / EMB);
    const float var = q * (1.0f / EMB) - mu * mu;
    const float inv = rsqrtf(var + 1e-5f);

    float* orow = out + row * (long)EMB;
    orow[tid]       = (v0 - mu) * inv * g[tid]       + b[tid];
    orow[tid + 128] = (v1 - mu) * inv * g[tid + 128] + b[tid + 128];
    orow[tid + 256] = (v2 - mu) * inv * g[tid + 256] + b[tid + 256];
}

// ---------------------------------------------------------------------------
// Causal softmax over scores[b, t, :]: cols > t masked; masked probs -> 0
// so the following dense S@V GEMM is correct. 256 threads = 1 col each.
// ---------------------------------------------------------------------------
__global__ __launch_bounds__(256)
void softmax_causal(float* __restrict__ att)
{
    const int t  = blockIdx.x;
    const int bb = blockIdx.y;
    float* row = att + ((long)bb * SEQ + t) * SEQ;
    const int c = threadIdx.x;

    float v = (c <= t) ? row[c] : -1e30f;

    __shared__ float sm[8];
    const int lane = c & 31, w = c >> 5;

    float m = v;
#pragma unroll
    for (int o = 16; o; o >>= 1) m = fmaxf(m, __shfl_down_sync(0xffffffffu, m, o));
    if (!lane) sm[w] = m;
    __syncthreads();
    m = fmaxf(fmaxf(fmaxf(sm[0], sm[1]), fmaxf(sm[2], sm[3])),
              fmaxf(fmaxf(sm[4], sm[5]), fmaxf(sm[6], sm[7])));

    const float e = (c <= t) ? expf(v - m) : 0.0f;
    float s = e;
    __syncthreads();                       // all reads of sm (max) done
#pragma unroll
    for (int o = 16; o; o >>= 1) s += __shfl_down_sync(0xffffffffu, s, o);
    if (!lane) sm[w] = s;
    __syncthreads();
    s = sm[0] + sm[1] + sm[2] + sm[3] + sm[4] + sm[5] + sm[6] + sm[7];

    row[c] = e * (1.0f / s);
}

// ---------------------------------------------------------------------------
// SGEMM: C[z] = epilogue( alpha * A[z] @ op(B[z]) )
//   A: [M,K] row-major, lda / batch stride sA
//   B: NN -> [K,N] row-major ldb;  NT (TRANSB) -> [N,K] row-major ldb
//   epilogue: (+bias[n]) (relu) (+R[z][m,n] with ld=ldc)
// Tiles: 128x128x8, 256 threads, 8x8 per thread. ALL dims assumed to divide
// exactly (verified for every call site). All pointers/lds 16B-vector safe.
// ---------------------------------------------------------------------------
template<bool TRANSB, bool BIAS, bool RELU, bool RESID>
__global__ __launch_bounds__(256)
void sgemm128(const float* __restrict__ A, int lda, long sA,
              const float* __restrict__ B, int ldb, long sB,
              const float* __restrict__ bias,
              const float* __restrict__ R, long sR,
              float* __restrict__ C, int ldc, long sC,
              int K, float alpha)
{
    __shared__ float As[8][128];
    __shared__ float Bs[8][128];

    const int z  = blockIdx.z;
    const float* Ab = A + (long)z * sA;
    const float* Bb = B + (long)z * sB;
    float*       Cb = C + (long)z * sC;

    const int tid = threadIdx.x;
    const int m0 = blockIdx.y * 128;
    const int n0 = blockIdx.x * 128;

    // A loader: 128 rows x 8 cols; tid -> (row = tid/2, col = (tid&1)*4)
    const int arow = tid >> 1;
    const int acol = (tid & 1) * 4;

    float acc[8][8];
#pragma unroll
    for (int i = 0; i < 8; i++)
#pragma unroll
        for (int j = 0; j < 8; j++) acc[i][j] = 0.0f;

    const int ty = tid >> 4;   // 0..15 -> C row group
    const int tx = tid & 15;   // 0..15 -> C col group

    for (int k0 = 0; k0 < K; k0 += 8) {
        // --- load A tile (transposed into As[k][m]) ---
        {
            float4 av = *(const float4*)(Ab + (long)(m0 + arow) * lda + k0 + acol);
            As[acol + 0][arow] = av.x;
            As[acol + 1][arow] = av.y;
            As[acol + 2][arow] = av.z;
            As[acol + 3][arow] = av.w;
        }
        // --- load B tile into Bs[k][n] ---
        if (!TRANSB) {
            const int brow = tid >> 5;          // 0..7
            const int bcol = (tid & 31) * 4;    // 0..124
            float4 bv = *(const float4*)(Bb + (long)(k0 + brow) * ldb + n0 + bcol);
            *(float4*)&Bs[brow][bcol] = bv;
        } else {
            const int bn = tid >> 1;            // 0..127
            const int bk = (tid & 1) * 4;       // 0 or 4
            float4 bv = *(const float4*)(Bb + (long)(n0 + bn) * ldb + k0 + bk);
            Bs[bk + 0][bn] = bv.x;
            Bs[bk + 1][bn] = bv.y;
            Bs[bk + 2][bn] = bv.z;
            Bs[bk + 3][bn] = bv.w;
        }
        __syncthreads();

#pragma unroll
        for (int kk = 0; kk < 8; kk++) {
            float a[8], b[8];
            *(float4*)(a)     = *(const float4*)&As[kk][ty * 8];
            *(float4*)(a + 4) = *(const float4*)&As[kk][ty * 8 + 4];
            *(float4*)(b)     = *(const float4*)&Bs[kk][tx * 8];
            *(float4*)(b + 4) = *(const float4*)&Bs[kk][tx * 8 + 4];
#pragma unroll
            for (int i = 0; i < 8; i++)
#pragma unroll
                for (int j = 0; j < 8; j++)
                    acc[i][j] += a[i] * b[j];
        }
        __syncthreads();
    }

    // --- epilogue ---
#pragma unroll
    for (int i = 0; i < 8; i++) {
        const long row = m0 + ty * 8 + i;
#pragma unroll
        for (int j = 0; j < 8; j += 4) {
            const int col = n0 + tx * 8 + j;
            float4 v;
            v.x = acc[i][j + 0] * alpha;
            v.y = acc[i][j + 1] * alpha;
            v.z = acc[i][j + 2] * alpha;
            v.w = acc[i][j + 3] * alpha;
            if (BIAS) {
                v.x += bias[col + 0];
                v.y += bias[col + 1];
                v.z += bias[col + 2];
                v.w += bias[col + 3];
            }
            if (RELU) {
                v.x = fmaxf(v.x, 0.0f);
                v.y = fmaxf(v.y, 0.0f);
                v.z = fmaxf(v.z, 0.0f);
                v.w = fmaxf(v.w, 0.0f);
            }
            if (RESID) {
                float4 r = *(const float4*)(R + (long)z * sR + row * ldc + col);
                v.x += r.x; v.y += r.y; v.z += r.z; v.w += r.w;
            }
            *(float4*)(Cb + row * ldc + col) = v;
        }
    }
}

// ---------------------------------------------------------------------------
// Launch
// ---------------------------------------------------------------------------
extern "C" void kernel_launch(void* const* d_in, const int* /*in_sizes*/, int /*n_in*/,
                              void* d_out, int /*out_size*/)
{
    const float* x      = (const float*)d_in[0];
    const float* W_attn = (const float*)d_in[1];
    const float* b_attn = (const float*)d_in[2];
    const float* W_proj = (const float*)d_in[3];
    const float* b_proj = (const float*)d_in[4];
    const float* ln1_g  = (const float*)d_in[5];
    const float* ln1_b  = (const float*)d_in[6];
    const float* ln2_g  = (const float*)d_in[7];
    const float* ln2_b  = (const float*)d_in[8];
    const float* W1     = (const float*)d_in[9];
    const float* b1     = (const float*)d_in[10];
    const float* W2     = (const float*)d_in[11];
    const float* b2     = (const float*)d_in[12];
    float* out = (float*)d_out;

    float *h, *qkv, *att, *x1, *f;
    cudaGetSymbolAddress((void**)&h,   g_h);
    cudaGetSymbolAddress((void**)&qkv, g_qkv);
    cudaGetSymbolAddress((void**)&att, g_att);
    cudaGetSymbolAddress((void**)&x1,  g_x1);
    cudaGetSymbolAddress((void**)&f,   g_f);

    const float inv_sqrt_c = 0.05103103630798287f;   // 1/sqrt(384)
    const long sQKV = (long)SEQ * (3 * EMB);         // per-batch stride into qkv
    const long sATT = (long)SEQ * SEQ;

    // 1. h = LN1(x)
    ln_kernel<<<MROWS, 128>>>(x, ln1_g, ln1_b, h);

    // 2. qkv = h @ W_attn + b_attn         [32768,384]x[384,1152]
    sgemm128<false, true, false, false><<<dim3(9, 256, 1), 256>>>(
        h, EMB, 0, W_attn, 3 * EMB, 0, b_attn, nullptr, 0,
        qkv, 3 * EMB, 0, EMB, 1.0f);

    // 3. S[b] = q[b] @ k[b]^T * 1/sqrt(C)   batched NT, M=N=256, K=384
    sgemm128<true, false, false, false><<<dim3(2, 2, BATCH), 256>>>(
        qkv, 3 * EMB, sQKV, qkv + EMB, 3 * EMB, sQKV, nullptr, nullptr, 0,
        att, SEQ, sATT, EMB, inv_sqrt_c);

    // 4. causal softmax rows (masked probs -> 0)
    softmax_causal<<<dim3(SEQ, BATCH), 256>>>(att);

    // 5. y[b] = S[b] @ v[b]                 batched NN, M=256, N=384, K=256
    sgemm128<false, false, false, false><<<dim3(3, 2, BATCH), 256>>>(
        att, SEQ, sATT, qkv + 2 * EMB, 3 * EMB, sQKV, nullptr, nullptr, 0,
        h, EMB, (long)SEQ * EMB, SEQ, 1.0f);

    // 6. x1 = x + y @ W_proj + b_proj
    sgemm128<false, true, false, true><<<dim3(3, 256, 1), 256>>>(
        h, EMB, 0, W_proj, EMB, 0, b_proj, x, 0,
        x1, EMB, 0, EMB, 1.0f);

    // 7. h2 = LN2(x1)   (reuses g_h)
    ln_kernel<<<MROWS, 128>>>(x1, ln2_g, ln2_b, h);

    // 8. f = relu(h2 @ W1 + b1)             [32768,384]x[384,1536]
    sgemm128<false, true, true, false><<<dim3(12, 256, 1), 256>>>(
        h, EMB, 0, W1, 4 * EMB, 0, b1, nullptr, 0,
        f, 4 * EMB, 0, EMB, 1.0f);

    // 9. out = x1 + f @ W2 + b2             [32768,1536]x[1536,384]
    sgemm128<false, true, false, true><<<dim3(3, 256, 1), 256>>>(
        f, 4 * EMB, 0, W2, EMB, 0, b2, x1, 0,
        out, EMB, 0, 4 * EMB, 1.0f);
}

// round 10
// speedup vs baseline: 2.8610x; 2.8610x over previous
#include <cuda_runtime.h>
#include <math.h>
#include <stdint.h>

// ---------------------------------------------------------------------------
// TransformerBlock B=128, T=256, C=384 — tf32 mma.sync tensor-core version.
// (tcgen05 unavailable: harness compiles via compute_103 virtual arch, which
// rejects all sm_103a-suffix features. mma.sync m16n8k8 tf32 is baseline.)
//
// GEMM: 128x128 tiles, 8 warps (2x4), each warp 64x32 via 4x4 m16n8k8 frags.
// K chunks of 16, double-buffered SMEM, conflict-free fragment pitches.
// Fused epilogue: alpha / bias / relu / residual. NN reads B[K,N] directly;
// NT (Q.K^T) reads [N,K] K-major natively -> no transpose kernels at all.
// ---------------------------------------------------------------------------

#define BATCH 128
#define SEQ   256
#define EMB   384
#define MROWS (BATCH * SEQ)   // 32768

#define PA    20              // A / NT-B smem pitch (floats): banks (20g+t)%32 all distinct
#define PBN   136             // NN-B smem pitch (floats):     banks (8t+g)%32 all distinct
#define A_FLOATS (128 * PA)   // 2560 floats = 10240 B
#define STAGE_FLOATS (2 * A_FLOATS)   // A + B per stage

// --------------------------- device scratch --------------------------------
__device__ float g_h  [(size_t)MROWS * EMB];            // LN1 out / attn y / LN2 out
__device__ float g_qkv[(size_t)MROWS * 3 * EMB];
__device__ float g_att[(size_t)BATCH * SEQ * SEQ];
__device__ float g_x1 [(size_t)MROWS * EMB];
__device__ float g_f  [(size_t)MROWS * 4 * EMB];

// ----------------------------- helpers -------------------------------------
__device__ __forceinline__ uint32_t tf32_of(float f) {
    uint32_t u;
    asm("cvt.rna.tf32.f32 %0, %1;" : "=r"(u) : "f"(f));
    return u;
}

__device__ __forceinline__ void mma_16x8x8(float* d, const uint32_t* a, const uint32_t* b) {
    asm volatile(
        "mma.sync.aligned.m16n8k8.row.col.f32.tf32.tf32.f32 "
        "{%0,%1,%2,%3}, {%4,%5,%6,%7}, {%8,%9}, {%0,%1,%2,%3};"
        : "+f"(d[0]), "+f"(d[1]), "+f"(d[2]), "+f"(d[3])
        : "r"(a[0]), "r"(a[1]), "r"(a[2]), "r"(a[3]), "r"(b[0]), "r"(b[1]));
}

// ---------------------------------------------------------------------------
// LayerNorm: one block per row, 128 threads, 3 elems/thread (C=384).
// ---------------------------------------------------------------------------
__global__ __launch_bounds__(128)
void ln_kernel(const float* __restrict__ x, const float* __restrict__ g,
               const float* __restrict__ b, float* __restrict__ out)
{
    const long row = blockIdx.x;
    const float* xr = x + row * (long)EMB;
    const int tid = threadIdx.x;

    float v0 = xr[tid], v1 = xr[tid + 128], v2 = xr[tid + 256];
    float s = v0 + v1 + v2;
    float q = v0 * v0 + v1 * v1 + v2 * v2;

    __shared__ float ss[4], qq[4];
    const int lane = tid & 31, w = tid >> 5;
#pragma unroll
    for (int o = 16; o; o >>= 1) {
        s += __shfl_down_sync(0xffffffffu, s, o);
        q += __shfl_down_sync(0xffffffffu, q, o);
    }
    if (!lane) { ss[w] = s; qq[w] = q; }
    __syncthreads();
    s = ss[0] + ss[1] + ss[2] + ss[3];
    q = qq[0] + qq[1] + qq[2] + qq[3];

    const float mu  = s * (1.0f / EMB);
    const float var = q * (1.0f / EMB) - mu * mu;
    const float inv = rsqrtf(var + 1e-5f);

    float* orow = out + row * (long)EMB;
    orow[tid]       = (v0 - mu) * inv * g[tid]       + b[tid];
    orow[tid + 128] = (v1 - mu) * inv * g[tid + 128] + b[tid + 128];
    orow[tid + 256] = (v2 - mu) * inv * g[tid + 256] + b[tid + 256];
}

// ---------------------------------------------------------------------------
// Causal softmax: masked probs -> 0 so the dense S@V GEMM is correct.
// ---------------------------------------------------------------------------
__global__ __launch_bounds__(256)
void softmax_causal(float* __restrict__ att)
{
    const int t  = blockIdx.x;
    const int bb = blockIdx.y;
    float* row = att + ((long)bb * SEQ + t) * SEQ;
    const int c = threadIdx.x;

    float v = (c <= t) ? row[c] : -1e30f;

    __shared__ float sm[8];
    const int lane = c & 31, w = c >> 5;

    float m = v;
#pragma unroll
    for (int o = 16; o; o >>= 1) m = fmaxf(m, __shfl_down_sync(0xffffffffu, m, o));
    if (!lane) sm[w] = m;
    __syncthreads();
    m = fmaxf(fmaxf(fmaxf(sm[0], sm[1]), fmaxf(sm[2], sm[3])),
              fmaxf(fmaxf(sm[4], sm[5]), fmaxf(sm[6], sm[7])));

    const float e = (c <= t) ? expf(v - m) : 0.0f;
    float s = e;
    __syncthreads();
#pragma unroll
    for (int o = 16; o; o >>= 1) s += __shfl_down_sync(0xffffffffu, s, o);
    if (!lane) sm[w] = s;
    __syncthreads();
    s = sm[0] + sm[1] + sm[2] + sm[3] + sm[4] + sm[5] + sm[6] + sm[7];

    row[c] = e * (1.0f / s);
}

// ---------------------------------------------------------------------------
// tf32 tensor-core GEMM:  C[z] = epi( alpha * A[z] @ op(B[z]) )
//   A  [M,K] row-major (lda, batch stride sA)
//   B  NN: [K,N] row-major (ldb) ; NT: [N,K] row-major (ldb)
// Tile 128x128, K in chunks of 16. M,N multiples of 128, K multiple of 16.
// Epilogue: (+bias[n]) (relu) (+R[z][m,n], stride ldc).
// ---------------------------------------------------------------------------
template<bool TRANSB, bool BIAS, bool RELU, bool RESID>
__global__ __launch_bounds__(256)
void tmma(const float* __restrict__ A, int lda, long sA,
          const float* __restrict__ B, int ldb, long sB,
          const float* __restrict__ bias,
          const float* __restrict__ R, long sR,
          float* __restrict__ C, int ldc, long sC,
          int K, float alpha)
{
    __shared__ float smbuf[2][STAGE_FLOATS];

    const int tid  = threadIdx.x;
    const int lane = tid & 31;
    const int wid  = tid >> 5;
    const int warpM = wid >> 2;      // 0..1  -> 64-row half
    const int warpN = wid & 3;       // 0..3  -> 32-col quarter
    const int g  = lane >> 2;        // 0..7
    const int tg = lane & 3;         // 0..3

    const int  z  = blockIdx.z;
    const long m0 = (long)blockIdx.y * 128;
    const int  n0 = blockIdx.x * 128;

    const float* Az = A + (long)z * sA + m0 * lda;
    const float* Bz = B + (long)z * sB + (TRANSB ? (long)n0 * ldb : (long)n0);

    // loader indices
    const int aRow = tid >> 2;            // 0..63 (and +64)
    const int aCol = (tid & 3) * 4;       // 0,4,8,12
    const int bKr  = tid >> 5;            // NN: 0..7 (and +8)
    const int bNc  = (tid & 31) * 4;      // NN: 0..124

    float acc[4][4][4];
#pragma unroll
    for (int i = 0; i < 4; i++)
#pragma unroll
        for (int j = 0; j < 4; j++)
#pragma unroll
            for (int r = 0; r < 4; r++) acc[i][j][r] = 0.0f;

    const int nc = K >> 4;

    float4 pa0, pa1, pb0, pb1;
    // prefetch chunk 0
    pa0 = *(const float4*)(Az + (long)aRow * lda + aCol);
    pa1 = *(const float4*)(Az + (long)(aRow + 64) * lda + aCol);
    if (TRANSB) {
        pb0 = *(const float4*)(Bz + (long)aRow * ldb + aCol);
        pb1 = *(const float4*)(Bz + (long)(aRow + 64) * ldb + aCol);
    } else {
        pb0 = *(const float4*)(Bz + (long)bKr * ldb + bNc);
        pb1 = *(const float4*)(Bz + (long)(bKr + 8) * ldb + bNc);
    }
    {
        float* sa = smbuf[0];
        float* sb = smbuf[0] + A_FLOATS;
        *(float4*)(sa + aRow * PA + aCol)        = pa0;
        *(float4*)(sa + (aRow + 64) * PA + aCol) = pa1;
        if (TRANSB) {
            *(float4*)(sb + aRow * PA + aCol)        = pb0;
            *(float4*)(sb + (aRow + 64) * PA + aCol) = pb1;
        } else {
            *(float4*)(sb + bKr * PBN + bNc)       = pb0;
            *(float4*)(sb + (bKr + 8) * PBN + bNc) = pb1;
        }
    }
    __syncthreads();

    for (int c = 0; c < nc; c++) {
        // prefetch next chunk to registers
        if (c + 1 < nc) {
            const int k0 = (c + 1) << 4;
            pa0 = *(const float4*)(Az + (long)aRow * lda + k0 + aCol);
            pa1 = *(const float4*)(Az + (long)(aRow + 64) * lda + k0 + aCol);
            if (TRANSB) {
                pb0 = *(const float4*)(Bz + (long)aRow * ldb + k0 + aCol);
                pb1 = *(const float4*)(Bz + (long)(aRow + 64) * ldb + k0 + aCol);
            } else {
                pb0 = *(const float4*)(Bz + (long)(k0 + bKr) * ldb + bNc);
                pb1 = *(const float4*)(Bz + (long)(k0 + bKr + 8) * ldb + bNc);
            }
        }

        // compute current chunk
        {
            const float* sa = smbuf[c & 1];
            const float* sb = smbuf[c & 1] + A_FLOATS;
#pragma unroll
            for (int ks = 0; ks < 2; ks++) {
                const int kb = ks * 8;
                uint32_t bf[4][2];
#pragma unroll
                for (int j = 0; j < 4; j++) {
                    const int nn = warpN * 32 + j * 8 + g;
                    if (TRANSB) {
                        bf[j][0] = tf32_of(sb[nn * PA + kb + tg]);
                        bf[j][1] = tf32_of(sb[nn * PA + kb + tg + 4]);
                    } else {
                        bf[j][0] = tf32_of(sb[(kb + tg) * PBN + nn]);
                        bf[j][1] = tf32_of(sb[(kb + tg + 4) * PBN + nn]);
                    }
                }
#pragma unroll
                for (int i = 0; i < 4; i++) {
                    const int r = warpM * 64 + i * 16 + g;
                    uint32_t af[4];
                    af[0] = tf32_of(sa[r * PA + kb + tg]);
                    af[1] = tf32_of(sa[(r + 8) * PA + kb + tg]);
                    af[2] = tf32_of(sa[r * PA + kb + tg + 4]);
                    af[3] = tf32_of(sa[(r + 8) * PA + kb + tg + 4]);
#pragma unroll
                    for (int j = 0; j < 4; j++)
                        mma_16x8x8(acc[i][j], af, bf[j]);
                }
            }
        }

        // store prefetched chunk to the other buffer (previous compute on it
        // finished before the last __syncthreads)
        if (c + 1 < nc) {
            float* sa = smbuf[(c + 1) & 1];
            float* sb = smbuf[(c + 1) & 1] + A_FLOATS;
            *(float4*)(sa + aRow * PA + aCol)        = pa0;
            *(float4*)(sa + (aRow + 64) * PA + aCol) = pa1;
            if (TRANSB) {
                *(float4*)(sb + aRow * PA + aCol)        = pb0;
                *(float4*)(sb + (aRow + 64) * PA + aCol) = pb1;
            } else {
                *(float4*)(sb + bKr * PBN + bNc)       = pb0;
                *(float4*)(sb + (bKr + 8) * PBN + bNc) = pb1;
            }
        }
        __syncthreads();
    }

    // ----------------------------- epilogue --------------------------------
    float* Cz = C + (long)z * sC;
    const float* Rz = RESID ? (R + (long)z * sR) : nullptr;

#pragma unroll
    for (int i = 0; i < 4; i++) {
        const long r0 = m0 + warpM * 64 + i * 16 + g;
        const long r1 = r0 + 8;
#pragma unroll
        for (int j = 0; j < 4; j++) {
            const int cc = n0 + warpN * 32 + j * 8 + tg * 2;
            float2 v0, v1;
            v0.x = acc[i][j][0] * alpha; v0.y = acc[i][j][1] * alpha;
            v1.x = acc[i][j][2] * alpha; v1.y = acc[i][j][3] * alpha;
            if (BIAS) {
                const float2 bv = *(const float2*)(bias + cc);
                v0.x += bv.x; v0.y += bv.y;
                v1.x += bv.x; v1.y += bv.y;
            }
            if (RELU) {
                v0.x = fmaxf(v0.x, 0.0f); v0.y = fmaxf(v0.y, 0.0f);
                v1.x = fmaxf(v1.x, 0.0f); v1.y = fmaxf(v1.y, 0.0f);
            }
            if (RESID) {
                const float2 q0 = *(const float2*)(Rz + r0 * ldc + cc);
                const float2 q1 = *(const float2*)(Rz + r1 * ldc + cc);
                v0.x += q0.x; v0.y += q0.y;
                v1.x += q1.x; v1.y += q1.y;
            }
            *(float2*)(Cz + r0 * ldc + cc) = v0;
            *(float2*)(Cz + r1 * ldc + cc) = v1;
        }
    }
}

// ---------------------------------------------------------------------------
// Launch
// ---------------------------------------------------------------------------
extern "C" void kernel_launch(void* const* d_in, const int* /*in_sizes*/, int /*n_in*/,
                              void* d_out, int /*out_size*/)
{
    const float* x      = (const float*)d_in[0];
    const float* W_attn = (const float*)d_in[1];
    const float* b_attn = (const float*)d_in[2];
    const float* W_proj = (const float*)d_in[3];
    const float* b_proj = (const float*)d_in[4];
    const float* ln1_g  = (const float*)d_in[5];
    const float* ln1_b  = (const float*)d_in[6];
    const float* ln2_g  = (const float*)d_in[7];
    const float* ln2_b  = (const float*)d_in[8];
    const float* W1     = (const float*)d_in[9];
    const float* b1     = (const float*)d_in[10];
    const float* W2     = (const float*)d_in[11];
    const float* b2     = (const float*)d_in[12];
    float* out = (float*)d_out;

    float *h, *qkv, *att, *x1, *f;
    cudaGetSymbolAddress((void**)&h,   g_h);
    cudaGetSymbolAddress((void**)&qkv, g_qkv);
    cudaGetSymbolAddress((void**)&att, g_att);
    cudaGetSymbolAddress((void**)&x1,  g_x1);
    cudaGetSymbolAddress((void**)&f,   g_f);

    const float inv_sqrt_c = 0.05103103630798287f;   // 1/sqrt(384)
    const long sQKV = (long)SEQ * (3 * EMB);
    const long sATT = (long)SEQ * SEQ;

    // 1. h = LN1(x)
    ln_kernel<<<MROWS, 128>>>(x, ln1_g, ln1_b, h);

    // 2. qkv = h @ W_attn + b_attn       M=32768, N=1152, K=384  (NN)
    tmma<false, true, false, false><<<dim3(9, 256, 1), 256>>>(
        h, EMB, 0, W_attn, 3 * EMB, 0, b_attn, nullptr, 0,
        qkv, 3 * EMB, 0, EMB, 1.0f);

    // 3. S[z] = q[z] @ k[z]^T / sqrt(C)  M=N=256, K=384          (NT)
    tmma<true, false, false, false><<<dim3(2, 2, BATCH), 256>>>(
        qkv, 3 * EMB, sQKV, qkv + EMB, 3 * EMB, sQKV, nullptr, nullptr, 0,
        att, SEQ, sATT, EMB, inv_sqrt_c);

    // 4. causal softmax (masked -> 0)
    softmax_causal<<<dim3(SEQ, BATCH), 256>>>(att);

    // 5. y[z] = S[z] @ V[z]              M=256, N=384, K=256     (NN)
    tmma<false, false, false, false><<<dim3(3, 2, BATCH), 256>>>(
        att, SEQ, sATT, qkv + 2 * EMB, 3 * EMB, sQKV, nullptr, nullptr, 0,
        h, EMB, (long)SEQ * EMB, SEQ, 1.0f);

    // 6. x1 = x + y @ W_proj + b_proj    M=32768, N=384, K=384   (NN)
    tmma<false, true, false, true><<<dim3(3, 256, 1), 256>>>(
        h, EMB, 0, W_proj, EMB, 0, b_proj, x, 0,
        x1, EMB, 0, EMB, 1.0f);

    // 7. h2 = LN2(x1)   (reuses g_h)
    ln_kernel<<<MROWS, 128>>>(x1, ln2_g, ln2_b, h);

    // 8. f = relu(h2 @ W1 + b1)          M=32768, N=1536, K=384  (NN)
    tmma<false, true, true, false><<<dim3(12, 256, 1), 256>>>(
        h, EMB, 0, W1, 4 * EMB, 0, b1, nullptr, 0,
        f, 4 * EMB, 0, EMB, 1.0f);

    // 9. out = x1 + f @ W2 + b2          M=32768, N=384, K=1536  (NN)
    tmma<false, true, false, true><<<dim3(3, 256, 1), 256>>>(
        f, 4 * EMB, 0, W2, EMB, 0, b2, x1, 0,
        out, EMB, 0, 4 * EMB, 1.0f);
}

// round 12
// speedup vs baseline: 2.8934x; 1.0113x over previous
#include <cuda_runtime.h>
#include <math.h>
#include <stdint.h>

// ---------------------------------------------------------------------------
// TransformerBlock B=128, T=256, C=384 — tf32 mma.sync + ldmatrix version.
// All GEMMs are NT: D[m,n] = sum_k A[m,k] * Bt[n,k]; weights & V transposed
// once by a cheap tiled-transpose kernel. tf32 conversion (cvt.rna) happens
// ONCE per element in the SMEM loader; the mainloop is pure ldmatrix + mma.
// 128x128 tile, 8 warps (2x4), warp tile 64x32, K chunks of 16, double-
// buffered SMEM at pitch 20 floats (conflict-free for ldmatrix & frags).
// ---------------------------------------------------------------------------

#define BATCH 128
#define SEQ   256
#define EMB   384
#define MROWS (BATCH * SEQ)   // 32768

#define PA       20                        // smem pitch (floats)
#define A_FLOATS (128 * PA)                // 2560 floats per operand tile
#define STAGE_FLOATS (2 * A_FLOATS)        // A + B
#define STAGE_BYTES  (STAGE_FLOATS * 4)    // 20480 B
#define A_BYTES      (A_FLOATS * 4)

// --------------------------- device scratch --------------------------------
__device__ float g_h  [(size_t)MROWS * EMB];            // LN1 out / attn y / LN2 out
__device__ float g_qkv[(size_t)MROWS * 3 * EMB];
__device__ float g_att[(size_t)BATCH * SEQ * SEQ];
__device__ float g_x1 [(size_t)MROWS * EMB];
__device__ float g_f  [(size_t)MROWS * 4 * EMB];
__device__ float g_vt [(size_t)BATCH * EMB * SEQ];      // V^T per batch [C,T]
__device__ float g_wta[(size_t)(3 * EMB) * EMB];        // W_attn^T
__device__ float g_wtp[(size_t)EMB * EMB];              // W_proj^T
__device__ float g_w1t[(size_t)(4 * EMB) * EMB];        // W1^T
__device__ float g_w2t[(size_t)EMB * (4 * EMB)];        // W2^T

// ----------------------------- helpers -------------------------------------
__device__ __forceinline__ uint32_t tf32_of(float f) {
    uint32_t u;
    asm("cvt.rna.tf32.f32 %0, %1;" : "=r"(u) : "f"(f));
    return u;
}

__device__ __forceinline__ void mma_16x8x8(float* d, const uint32_t* a, const uint32_t* b) {
    asm volatile(
        "mma.sync.aligned.m16n8k8.row.col.f32.tf32.tf32.f32 "
        "{%0,%1,%2,%3}, {%4,%5,%6,%7}, {%8,%9}, {%0,%1,%2,%3};"
        : "+f"(d[0]), "+f"(d[1]), "+f"(d[2]), "+f"(d[3])
        : "r"(a[0]), "r"(a[1]), "r"(a[2]), "r"(a[3]), "r"(b[0]), "r"(b[1]));
}

__device__ __forceinline__ void ldmx4(uint32_t* d, uint32_t addr) {
    asm volatile(
        "ldmatrix.sync.aligned.m8n8.x4.shared.b16 {%0,%1,%2,%3}, [%4];"
        : "=r"(d[0]), "=r"(d[1]), "=r"(d[2]), "=r"(d[3]) : "r"(addr));
}

// ---------------------------------------------------------------------------
// LayerNorm: one block per row, 128 threads, 3 elems/thread (C=384).
// ---------------------------------------------------------------------------
__global__ __launch_bounds__(128)
void ln_kernel(const float* __restrict__ x, const float* __restrict__ g,
               const float* __restrict__ b, float* __restrict__ out)
{
    const long row = blockIdx.x;
    const float* xr = x + row * (long)EMB;
    const int tid = threadIdx.x;

    float v0 = xr[tid], v1 = xr[tid + 128], v2 = xr[tid + 256];
    float s = v0 + v1 + v2;
    float q = v0 * v0 + v1 * v1 + v2 * v2;

    __shared__ float ss[4], qq[4];
    const int lane = tid & 31, w = tid >> 5;
#pragma unroll
    for (int o = 16; o; o >>= 1) {
        s += __shfl_down_sync(0xffffffffu, s, o);
        q += __shfl_down_sync(0xffffffffu, q, o);
    }
    if (!lane) { ss[w] = s; qq[w] = q; }
    __syncthreads();
    s = ss[0] + ss[1] + ss[2] + ss[3];
    q = qq[0] + qq[1] + qq[2] + qq[3];

    const float mu  = s * (1.0f / EMB);
    const float var = q * (1.0f / EMB) - mu * mu;
    const float inv = rsqrtf(var + 1e-5f);

    float* orow = out + row * (long)EMB;
    orow[tid]       = (v0 - mu) * inv * g[tid]       + b[tid];
    orow[tid + 128] = (v1 - mu) * inv * g[tid + 128] + b[tid + 128];
    orow[tid + 256] = (v2 - mu) * inv * g[tid + 256] + b[tid + 256];
}

// ---------------------------------------------------------------------------
// Causal softmax: masked probs -> 0 so the dense S@V GEMM is correct.
// ---------------------------------------------------------------------------
__global__ __launch_bounds__(256)
void softmax_causal(float* __restrict__ att)
{
    const int t  = blockIdx.x;
    const int bb = blockIdx.y;
    float* row = att + ((long)bb * SEQ + t) * SEQ;
    const int c = threadIdx.x;

    float v = (c <= t) ? row[c] : -1e30f;

    __shared__ float sm[8];
    const int lane = c & 31, w = c >> 5;

    float m = v;
#pragma unroll
    for (int o = 16; o; o >>= 1) m = fmaxf(m, __shfl_down_sync(0xffffffffu, m, o));
    if (!lane) sm[w] = m;
    __syncthreads();
    m = fmaxf(fmaxf(fmaxf(sm[0], sm[1]), fmaxf(sm[2], sm[3])),
              fmaxf(fmaxf(sm[4], sm[5]), fmaxf(sm[6], sm[7])));

    const float e = (c <= t) ? expf(v - m) : 0.0f;
    float s = e;
    __syncthreads();
#pragma unroll
    for (int o = 16; o; o >>= 1) s += __shfl_down_sync(0xffffffffu, s, o);
    if (!lane) sm[w] = s;
    __syncthreads();
    s = sm[0] + sm[1] + sm[2] + sm[3] + sm[4] + sm[5] + sm[6] + sm[7];

    row[c] = e * (1.0f / s);
}

// ---------------------------------------------------------------------------
// Tiled transpose: out[z][c][r] = in[z][r][c].  grid(cols/32, rows/32, z),
// block (32,8).
// ---------------------------------------------------------------------------
__global__ __launch_bounds__(256)
void transpose_k(const float* __restrict__ in, int ldi, long sI,
                 float* __restrict__ out, int ldo, long sO)
{
    __shared__ float t[32][33];
    const float* I = in + (long)blockIdx.z * sI;
    float*       O = out + (long)blockIdx.z * sO;
    const int r0 = blockIdx.y * 32, c0 = blockIdx.x * 32;
    const int tx = threadIdx.x, ty = threadIdx.y;
#pragma unroll
    for (int i = ty; i < 32; i += 8)
        t[i][tx] = I[(long)(r0 + i) * ldi + c0 + tx];
    __syncthreads();
#pragma unroll
    for (int i = ty; i < 32; i += 8)
        O[(long)(c0 + i) * ldo + r0 + tx] = t[tx][i];
}

// ---------------------------------------------------------------------------
// tf32 tensor-core NT GEMM:  C[z] = epi( alpha * A[z] @ Bt[z]^T )
//   A  [M,K] row-major (lda, batch stride sA)
//   Bt [N,K] row-major (ldb, batch stride sB)
// Tile 128x128, K in chunks of 16. M,N multiples of 128, K multiple of 16.
// Epilogue: (+bias[n]) (relu) (+R[z][m,n], stride ldc).
// ---------------------------------------------------------------------------
template<bool BIAS, bool RELU, bool RESID>
__global__ __launch_bounds__(256, 2)
void tmma(const float* __restrict__ A, int lda, long sA,
          const float* __restrict__ Bt, int ldb, long sB,
          const float* __restrict__ bias,
          const float* __restrict__ R, long sR,
          float* __restrict__ C, int ldc, long sC,
          int K, float alpha)
{
    __shared__ float smbuf[2][STAGE_FLOATS];

    const int tid  = threadIdx.x;
    const int lane = tid & 31;
    const int wid  = tid >> 5;
    const int warpM = wid >> 2;      // 0..1 -> 64-row half
    const int warpN = wid & 3;       // 0..3 -> 32-col quarter
    const int g  = lane >> 2;        // 0..7
    const int tg = lane & 3;         // 0..3

    const int  z  = blockIdx.z;
    const long m0 = (long)blockIdx.y * 128;
    const int  n0 = blockIdx.x * 128;

    const float* Az = A  + (long)z * sA + m0 * lda;
    const float* Bz = Bt + (long)z * sB + (long)n0 * ldb;

    // loader indices (both operands identical NT pattern)
    const int aRow = tid >> 2;            // 0..63 (and +64)
    const int aCol = (tid & 3) * 4;       // 0,4,8,12

    const uint32_t smb = (uint32_t)__cvta_generic_to_shared(&smbuf[0][0]);

    // per-lane ldmatrix fragment offsets (bytes, relative to operand base)
    //   A frag (x4, per i): row = warpM*64 + (lane&15) (+ i*16), col = (lane>>4)*4
    const uint32_t aFragOff =
        (uint32_t)(((warpM * 64 + (lane & 15)) * PA + (lane >> 4) * 4) * 4);
    //   B frags (x4 = two j's): row = warpN*32 + p*16 + ((lane>>4)&1)*8 + (lane&7)
    //                            col = ((lane>>3)&1)*4
    const uint32_t bFragOff0 =
        (uint32_t)(((warpN * 32 + ((lane >> 4) & 1) * 8 + (lane & 7)) * PA
                    + ((lane >> 3) & 1) * 4) * 4);
    const uint32_t bFragOff1 = bFragOff0 + (uint32_t)(16 * PA * 4);
    const uint32_t ldStOff = (uint32_t)((aRow * PA + aCol) * 4);   // loader STS

    float acc[4][4][4];
#pragma unroll
    for (int i = 0; i < 4; i++)
#pragma unroll
        for (int j = 0; j < 4; j++)
#pragma unroll
            for (int r = 0; r < 4; r++) acc[i][j][r] = 0.0f;

    const int nc = K >> 4;

    float4 pa0, pa1, pb0, pb1;
    // prefetch chunk 0
    pa0 = *(const float4*)(Az + (long)aRow * lda + aCol);
    pa1 = *(const float4*)(Az + (long)(aRow + 64) * lda + aCol);
    pb0 = *(const float4*)(Bz + (long)aRow * ldb + aCol);
    pb1 = *(const float4*)(Bz + (long)(aRow + 64) * ldb + aCol);
    {
        uint4 ua, ub;
        float* sa = smbuf[0];
        float* sb = smbuf[0] + A_FLOATS;
        ua.x = tf32_of(pa0.x); ua.y = tf32_of(pa0.y); ua.z = tf32_of(pa0.z); ua.w = tf32_of(pa0.w);
        *(uint4*)(sa + aRow * PA + aCol) = ua;
        ua.x = tf32_of(pa1.x); ua.y = tf32_of(pa1.y); ua.z = tf32_of(pa1.z); ua.w = tf32_of(pa1.w);
        *(uint4*)(sa + (aRow + 64) * PA + aCol) = ua;
        ub.x = tf32_of(pb0.x); ub.y = tf32_of(pb0.y); ub.z = tf32_of(pb0.z); ub.w = tf32_of(pb0.w);
        *(uint4*)(sb + aRow * PA + aCol) = ub;
        ub.x = tf32_of(pb1.x); ub.y = tf32_of(pb1.y); ub.z = tf32_of(pb1.z); ub.w = tf32_of(pb1.w);
        *(uint4*)(sb + (aRow + 64) * PA + aCol) = ub;
    }
    __syncthreads();

    for (int c = 0; c < nc; c++) {
        // prefetch next chunk to registers
        if (c + 1 < nc) {
            const int k0 = (c + 1) << 4;
            pa0 = *(const float4*)(Az + (long)aRow * lda + k0 + aCol);
            pa1 = *(const float4*)(Az + (long)(aRow + 64) * lda + k0 + aCol);
            pb0 = *(const float4*)(Bz + (long)aRow * ldb + k0 + aCol);
            pb1 = *(const float4*)(Bz + (long)(aRow + 64) * ldb + k0 + aCol);
        }

        // compute current chunk: pure ldmatrix + mma
        {
            const uint32_t sA32 = smb + (uint32_t)((c & 1) * STAGE_BYTES);
            const uint32_t sB32 = sA32 + (uint32_t)A_BYTES;
#pragma unroll
            for (int ks = 0; ks < 2; ks++) {
                const uint32_t kso = (uint32_t)(ks * 32);
                uint32_t b0[4], b1[4];
                ldmx4(b0, sB32 + bFragOff0 + kso);
                ldmx4(b1, sB32 + bFragOff1 + kso);
#pragma unroll
                for (int i = 0; i < 4; i++) {
                    uint32_t a[4];
                    ldmx4(a, sA32 + aFragOff + (uint32_t)(i * 16 * PA * 4) + kso);
                    mma_16x8x8(acc[i][0], a, b0);
                    mma_16x8x8(acc[i][1], a, b0 + 2);
                    mma_16x8x8(acc[i][2], a, b1);
                    mma_16x8x8(acc[i][3], a, b1 + 2);
                }
            }
        }

        // store prefetched chunk (cvt to tf32 once) into the other buffer
        if (c + 1 < nc) {
            uint4 ua, ub;
            float* sa = smbuf[(c + 1) & 1];
            float* sb = smbuf[(c + 1) & 1] + A_FLOATS;
            ua.x = tf32_of(pa0.x); ua.y = tf32_of(pa0.y); ua.z = tf32_of(pa0.z); ua.w = tf32_of(pa0.w);
            *(uint4*)(sa + aRow * PA + aCol) = ua;
            ua.x = tf32_of(pa1.x); ua.y = tf32_of(pa1.y); ua.z = tf32_of(pa1.z); ua.w = tf32_of(pa1.w);
            *(uint4*)(sa + (aRow + 64) * PA + aCol) = ua;
            ub.x = tf32_of(pb0.x); ub.y = tf32_of(pb0.y); ub.z = tf32_of(pb0.z); ub.w = tf32_of(pb0.w);
            *(uint4*)(sb + aRow * PA + aCol) = ub;
            ub.x = tf32_of(pb1.x); ub.y = tf32_of(pb1.y); ub.z = tf32_of(pb1.z); ub.w = tf32_of(pb1.w);
            *(uint4*)(sb + (aRow + 64) * PA + aCol) = ub;
        }
        __syncthreads();
    }

    // ----------------------------- epilogue --------------------------------
    float* Cz = C + (long)z * sC;
    const float* Rz = RESID ? (R + (long)z * sR) : nullptr;

#pragma unroll
    for (int i = 0; i < 4; i++) {
        const long r0 = m0 + warpM * 64 + i * 16 + g;
        const long r1 = r0 + 8;
#pragma unroll
        for (int j = 0; j < 4; j++) {
            const int cc = n0 + warpN * 32 + j * 8 + tg * 2;
            float2 v0, v1;
            v0.x = acc[i][j][0] * alpha; v0.y = acc[i][j][1] * alpha;
            v1.x = acc[i][j][2] * alpha; v1.y = acc[i][j][3] * alpha;
            if (BIAS) {
                const float2 bv = *(const float2*)(bias + cc);
                v0.x += bv.x; v0.y += bv.y;
                v1.x += bv.x; v1.y += bv.y;
            }
            if (RELU) {
                v0.x = fmaxf(v0.x, 0.0f); v0.y = fmaxf(v0.y, 0.0f);
                v1.x = fmaxf(v1.x, 0.0f); v1.y = fmaxf(v1.y, 0.0f);
            }
            if (RESID) {
                const float2 q0 = *(const float2*)(Rz + r0 * ldc + cc);
                const float2 q1 = *(const float2*)(Rz + r1 * ldc + cc);
                v0.x += q0.x; v0.y += q0.y;
                v1.x += q1.x; v1.y += q1.y;
            }
            *(float2*)(Cz + r0 * ldc + cc) = v0;
            *(float2*)(Cz + r1 * ldc + cc) = v1;
        }
    }
}

// ---------------------------------------------------------------------------
// Launch
// ---------------------------------------------------------------------------
extern "C" void kernel_launch(void* const* d_in, const int* /*in_sizes*/, int /*n_in*/,
                              void* d_out, int /*out_size*/)
{
    const float* x      = (const float*)d_in[0];
    const float* W_attn = (const float*)d_in[1];
    const float* b_attn = (const float*)d_in[2];
    const float* W_proj = (const float*)d_in[3];
    const float* b_proj = (const float*)d_in[4];
    const float* ln1_g  = (const float*)d_in[5];
    const float* ln1_b  = (const float*)d_in[6];
    const float* ln2_g  = (const float*)d_in[7];
    const float* ln2_b  = (const float*)d_in[8];
    const float* W1     = (const float*)d_in[9];
    const float* b1     = (const float*)d_in[10];
    const float* W2     = (const float*)d_in[11];
    const float* b2     = (const float*)d_in[12];
    float* out = (float*)d_out;

    float *h, *qkv, *att, *x1, *f, *vt, *wta, *wtp, *w1t, *w2t;
    cudaGetSymbolAddress((void**)&h,   g_h);
    cudaGetSymbolAddress((void**)&qkv, g_qkv);
    cudaGetSymbolAddress((void**)&att, g_att);
    cudaGetSymbolAddress((void**)&x1,  g_x1);
    cudaGetSymbolAddress((void**)&f,   g_f);
    cudaGetSymbolAddress((void**)&vt,  g_vt);
    cudaGetSymbolAddress((void**)&wta, g_wta);
    cudaGetSymbolAddress((void**)&wtp, g_wtp);
    cudaGetSymbolAddress((void**)&w1t, g_w1t);
    cudaGetSymbolAddress((void**)&w2t, g_w2t);

    const float inv_sqrt_c = 0.05103103630798287f;   // 1/sqrt(384)
    const long sQKV = (long)SEQ * (3 * EMB);
    const long sATT = (long)SEQ * SEQ;
    const dim3 tb(32, 8);

    // 0. one-time transposes: weights [K,N] -> [N,K]
    transpose_k<<<dim3((3 * EMB) / 32, EMB / 32, 1), tb>>>(W_attn, 3 * EMB, 0, wta, EMB, 0);
    transpose_k<<<dim3(EMB / 32, EMB / 32, 1),       tb>>>(W_proj, EMB, 0,     wtp, EMB, 0);
    transpose_k<<<dim3((4 * EMB) / 32, EMB / 32, 1), tb>>>(W1, 4 * EMB, 0,     w1t, EMB, 0);
    transpose_k<<<dim3(EMB / 32, (4 * EMB) / 32, 1), tb>>>(W2, EMB, 0,         w2t, 4 * EMB, 0);

    // 1. h = LN1(x)
    ln_kernel<<<MROWS, 128>>>(x, ln1_g, ln1_b, h);

    // 2. qkv = h @ W_attn + b_attn       M=32768, N=1152, K=384
    tmma<true, false, false><<<dim3(9, 256, 1), 256>>>(
        h, EMB, 0, wta, EMB, 0, b_attn, nullptr, 0,
        qkv, 3 * EMB, 0, EMB, 1.0f);

    // 3. Vt[z] = V[z]^T  ([T,C] -> [C,T])
    transpose_k<<<dim3(EMB / 32, SEQ / 32, BATCH), tb>>>(
        qkv + 2 * EMB, 3 * EMB, sQKV, vt, SEQ, (long)EMB * SEQ);

    // 4. S[z] = q[z] @ k[z]^T / sqrt(C)  M=N=256, K=384
    tmma<false, false, false><<<dim3(2, 2, BATCH), 256>>>(
        qkv, 3 * EMB, sQKV, qkv + EMB, 3 * EMB, sQKV, nullptr, nullptr, 0,
        att, SEQ, sATT, EMB, inv_sqrt_c);

    // 5. causal softmax (masked -> 0)
    softmax_causal<<<dim3(SEQ, BATCH), 256>>>(att);

    // 6. y[z] = S[z] @ V[z] via Vt       M=256, N=384, K=256
    tmma<false, false, false><<<dim3(3, 2, BATCH), 256>>>(
        att, SEQ, sATT, vt, SEQ, (long)EMB * SEQ, nullptr, nullptr, 0,
        h, EMB, (long)SEQ * EMB, SEQ, 1.0f);

    // 7. x1 = x + y @ W_proj + b_proj    M=32768, N=384, K=384
    tmma<true, false, true><<<dim3(3, 256, 1), 256>>>(
        h, EMB, 0, wtp, EMB, 0, b_proj, x, 0,
        x1, EMB, 0, EMB, 1.0f);

    // 8. h2 = LN2(x1)   (reuses g_h)
    ln_kernel<<<MROWS, 128>>>(x1, ln2_g, ln2_b, h);

    // 9. f = relu(h2 @ W1 + b1)          M=32768, N=1536, K=384
    tmma<true, true, false><<<dim3(12, 256, 1), 256>>>(
        h, EMB, 0, w1t, EMB, 0, b1, nullptr, 0,
        f, 4 * EMB, 0, EMB, 1.0f);

    // 10. out = x1 + f @ W2 + b2         M=32768, N=384, K=1536
    tmma<true, false, true><<<dim3(3, 256, 1), 256>>>(
        f, 4 * EMB, 0, w2t, 4 * EMB, 0, b2, x1, 0,
        out, EMB, 0, 4 * EMB, 1.0f);
}

// round 13
// speedup vs baseline: 5.0400x; 1.7419x over previous
#include <cuda_runtime.h>
#include <cuda_fp16.h>
#include <math.h>
#include <stdint.h>

// ---------------------------------------------------------------------------
// TransformerBlock B=128, T=256, C=384 — fp16 mma.sync (m16n8k16) version.
// All GEMM operands are fp16 in gmem (same 10-bit mantissa as tf32, 2x rate
// on the legacy mma path). fp32 accumulate everywhere; att logits, x1, out
// stay fp32. GEMM: 128x128 tile, 8 warps (2x4), warp 64x32, K chunks of 32,
// 3-stage cp.async pipeline, ldmatrix fragments, fused epilogue.
// ---------------------------------------------------------------------------

#define BATCH 128
#define SEQ   256
#define EMB   384
#define MROWS (BATCH * SEQ)   // 32768

#define PITCHB     80                      // smem row pitch bytes (32 fp16=64B data +16 pad)
#define OP_BYTES   (128 * PITCHB)          // 10240 per operand per stage
#define STAGE_BYTES (2 * OP_BYTES)         // 20480
#define NSTAGE     3
#define SMEM_DYN   (NSTAGE * STAGE_BYTES)  // 61440

// --------------------------- device scratch --------------------------------
__device__ __half g_h16  [(size_t)MROWS * EMB];          // LN1/LN2 out (fp16)
__device__ __half g_qkv16[(size_t)MROWS * 3 * EMB];
__device__ float  g_att  [(size_t)BATCH * SEQ * SEQ];    // logits (fp32)
__device__ __half g_att16[(size_t)BATCH * SEQ * SEQ];    // softmax probs (fp16)
__device__ __half g_y16  [(size_t)MROWS * EMB];
__device__ float  g_x1   [(size_t)MROWS * EMB];
__device__ __half g_f16  [(size_t)MROWS * 4 * EMB];
__device__ __half g_vt16 [(size_t)BATCH * EMB * SEQ];    // V^T per batch [C,T]
__device__ __half g_wta16[(size_t)(3 * EMB) * EMB];
__device__ __half g_wtp16[(size_t)EMB * EMB];
__device__ __half g_w1t16[(size_t)(4 * EMB) * EMB];
__device__ __half g_w2t16[(size_t)EMB * (4 * EMB)];

// ----------------------------- PTX helpers ---------------------------------
__device__ __forceinline__ void mma_16x8x16(float* d, const uint32_t* a, const uint32_t* b) {
    asm volatile(
        "mma.sync.aligned.m16n8k16.row.col.f32.f16.f16.f32 "
        "{%0,%1,%2,%3}, {%4,%5,%6,%7}, {%8,%9}, {%0,%1,%2,%3};"
        : "+f"(d[0]), "+f"(d[1]), "+f"(d[2]), "+f"(d[3])
        : "r"(a[0]), "r"(a[1]), "r"(a[2]), "r"(a[3]), "r"(b[0]), "r"(b[1]));
}

__device__ __forceinline__ void ldmx4(uint32_t* d, uint32_t addr) {
    asm volatile(
        "ldmatrix.sync.aligned.m8n8.x4.shared.b16 {%0,%1,%2,%3}, [%4];"
        : "=r"(d[0]), "=r"(d[1]), "=r"(d[2]), "=r"(d[3]) : "r"(addr));
}

#define CP16(dst, src) \
    asm volatile("cp.async.cg.shared.global [%0], [%1], 16;" :: "r"(dst), "l"(src))
#define CPCOMMIT() asm volatile("cp.async.commit_group;")
#define CPWAIT1()  asm volatile("cp.async.wait_group 1;")

// ---------------------------------------------------------------------------
// LayerNorm: fp32 in, fp16 out. One block per row, 128 threads.
// ---------------------------------------------------------------------------
__global__ __launch_bounds__(128)
void ln_kernel(const float* __restrict__ x, const float* __restrict__ g,
               const float* __restrict__ b, __half* __restrict__ out)
{
    const long row = blockIdx.x;
    const float* xr = x + row * (long)EMB;
    const int tid = threadIdx.x;

    float v0 = xr[tid], v1 = xr[tid + 128], v2 = xr[tid + 256];
    float s = v0 + v1 + v2;
    float q = v0 * v0 + v1 * v1 + v2 * v2;

    __shared__ float ss[4], qq[4];
    const int lane = tid & 31, w = tid >> 5;
#pragma unroll
    for (int o = 16; o; o >>= 1) {
        s += __shfl_down_sync(0xffffffffu, s, o);
        q += __shfl_down_sync(0xffffffffu, q, o);
    }
    if (!lane) { ss[w] = s; qq[w] = q; }
    __syncthreads();
    s = ss[0] + ss[1] + ss[2] + ss[3];
    q = qq[0] + qq[1] + qq[2] + qq[3];

    const float mu  = s * (1.0f / EMB);
    const float var = q * (1.0f / EMB) - mu * mu;
    const float inv = rsqrtf(var + 1e-5f);

    __half* orow = out + row * (long)EMB;
    orow[tid]       = __float2half((v0 - mu) * inv * g[tid]       + b[tid]);
    orow[tid + 128] = __float2half((v1 - mu) * inv * g[tid + 128] + b[tid + 128]);
    orow[tid + 256] = __float2half((v2 - mu) * inv * g[tid + 256] + b[tid + 256]);
}

// ---------------------------------------------------------------------------
// Causal softmax: fp32 logits in, fp16 probs out (masked -> 0).
// ---------------------------------------------------------------------------
__global__ __launch_bounds__(256)
void softmax_causal(const float* __restrict__ att, __half* __restrict__ outp)
{
    const int t  = blockIdx.x;
    const int bb = blockIdx.y;
    const long off = ((long)bb * SEQ + t) * SEQ;
    const float* row = att + off;
    const int c = threadIdx.x;

    float v = (c <= t) ? row[c] : -1e30f;

    __shared__ float sm[8];
    const int lane = c & 31, w = c >> 5;

    float m = v;
#pragma unroll
    for (int o = 16; o; o >>= 1) m = fmaxf(m, __shfl_down_sync(0xffffffffu, m, o));
    if (!lane) sm[w] = m;
    __syncthreads();
    m = fmaxf(fmaxf(fmaxf(sm[0], sm[1]), fmaxf(sm[2], sm[3])),
              fmaxf(fmaxf(sm[4], sm[5]), fmaxf(sm[6], sm[7])));

    const float e = (c <= t) ? expf(v - m) : 0.0f;
    float s = e;
    __syncthreads();
#pragma unroll
    for (int o = 16; o; o >>= 1) s += __shfl_down_sync(0xffffffffu, s, o);
    if (!lane) sm[w] = s;
    __syncthreads();
    s = sm[0] + sm[1] + sm[2] + sm[3] + sm[4] + sm[5] + sm[6] + sm[7];

    outp[off + c] = __float2half(e * (1.0f / s));
}

// ---------------------------------------------------------------------------
// Transpose fp32 -> fp16:  out[c][r] = (half)in[r][c]
// ---------------------------------------------------------------------------
__global__ __launch_bounds__(256)
void tr_w(const float* __restrict__ in, int ldi, __half* __restrict__ out, int ldo)
{
    __shared__ float t[32][33];
    const int r0 = blockIdx.y * 32, c0 = blockIdx.x * 32;
    const int tx = threadIdx.x, ty = threadIdx.y;
#pragma unroll
    for (int i = ty; i < 32; i += 8)
        t[i][tx] = in[(long)(r0 + i) * ldi + c0 + tx];
    __syncthreads();
#pragma unroll
    for (int i = ty; i < 32; i += 8)
        out[(long)(c0 + i) * ldo + r0 + tx] = __float2half(t[tx][i]);
}

// ---------------------------------------------------------------------------
// Transpose fp16 -> fp16 (batched):  out[z][c][r] = in[z][r][c]
// ---------------------------------------------------------------------------
__global__ __launch_bounds__(256)
void tr_h(const __half* __restrict__ in, int ldi, long sI,
          __half* __restrict__ out, int ldo, long sO)
{
    __shared__ __half t[32][34];
    const __half* I = in + (long)blockIdx.z * sI;
    __half*       O = out + (long)blockIdx.z * sO;
    const int r0 = blockIdx.y * 32, c0 = blockIdx.x * 32;
    const int tx = threadIdx.x, ty = threadIdx.y;
#pragma unroll
    for (int i = ty; i < 32; i += 8)
        t[i][tx] = I[(long)(r0 + i) * ldi + c0 + tx];
    __syncthreads();
#pragma unroll
    for (int i = ty; i < 32; i += 8)
        O[(long)(c0 + i) * ldo + r0 + tx] = t[tx][i];
}

// ---------------------------------------------------------------------------
// fp16 tensor-core NT GEMM:  C[z] = epi( alpha * A[z] @ Bt[z]^T )
//   A  [M,K] fp16 row-major (lda halves, batch stride sA)
//   Bt [N,K] fp16 row-major (ldb halves, batch stride sB)
// 128x128 tile, K chunks of 32, 3-stage cp.async pipeline.
// M,N multiples of 128; K multiple of 32, K/32 >= 2.
// OUTH: C is fp16 (ldc halves); else fp32. bias/resid always fp32.
// ---------------------------------------------------------------------------
template<bool BIAS, bool RELU, bool RESID, bool OUTH>
__global__ __launch_bounds__(256, 2)
void hgemm(const __half* __restrict__ A, int lda, long sA,
           const __half* __restrict__ Bt, int ldb, long sB,
           const float* __restrict__ bias,
           const float* __restrict__ R, long sR,
           void* __restrict__ Cv, int ldc, long sC,
           int K, float alpha)
{
    extern __shared__ __align__(16) char smem[];
    const uint32_t smb = (uint32_t)__cvta_generic_to_shared(smem);

    const int tid  = threadIdx.x;
    const int lane = tid & 31;
    const int wid  = tid >> 5;
    const int warpM = wid >> 2;      // 0..1 -> 64-row half
    const int warpN = wid & 3;       // 0..3 -> 32-col quarter
    const int g  = lane >> 2;        // 0..7
    const int tg = lane & 3;         // 0..3

    const int  z  = blockIdx.z;
    const long m0 = (long)blockIdx.y * 128;
    const int  n0 = blockIdx.x * 128;

    const __half* Az = A  + (long)z * sA + m0 * lda;
    const __half* Bz = Bt + (long)z * sB + (long)n0 * ldb;

    // loader: thread -> (row = tid>>1, 32B half-row = (tid&1))
    const int rL = tid >> 1;
    const int qb = (tid & 1) * 2;                 // 16B-quarter base (0 or 2)
    const __half* Aro = Az + (long)rL * lda + qb * 8;
    const __half* Bro = Bz + (long)rL * ldb + qb * 8;
    const uint32_t aDst = smb + (uint32_t)(rL * PITCHB + qb * 16);
    const uint32_t bDst = aDst + OP_BYTES;

    // ldmatrix per-lane fragment offsets (bytes within operand tile)
    const uint32_t aOff =
        (uint32_t)((warpM * 64 + (lane & 7) + ((lane >> 3) & 1) * 8) * PITCHB
                   + ((lane >> 4) & 1) * 16);
    const uint32_t bOff =
        (uint32_t)((warpN * 32 + (lane & 7) + ((lane >> 4) & 1) * 8) * PITCHB
                   + ((lane >> 3) & 1) * 16);

    float acc[4][4][4];
#pragma unroll
    for (int i = 0; i < 4; i++)
#pragma unroll
        for (int j = 0; j < 4; j++)
#pragma unroll
            for (int r = 0; r < 4; r++) acc[i][j][r] = 0.0f;

    const int nc = K >> 5;

    // prologue: chunks 0 and 1
#pragma unroll
    for (int c = 0; c < 2; c++) {
        const uint32_t st = (uint32_t)(c * STAGE_BYTES);
        CP16(aDst + st,      Aro + c * 32);
        CP16(aDst + st + 16, Aro + c * 32 + 8);
        CP16(bDst + st,      Bro + c * 32);
        CP16(bDst + st + 16, Bro + c * 32 + 8);
        CPCOMMIT();
    }

    int sc = 0;                 // stage of chunk c
    for (int c = 0; c < nc; c++) {
        CPWAIT1();              // chunk c resident
        __syncthreads();        // all warps done with stage (c-1)%3 compute

        // issue chunk c+2 into stage (c+2)%3  (== (c-1)%3, now free)
        {
            int s2 = sc + 2; if (s2 >= NSTAGE) s2 -= NSTAGE;
            const uint32_t st = (uint32_t)(s2 * STAGE_BYTES);
            if (c + 2 < nc) {
                CP16(aDst + st,      Aro + (c + 2) * 32);
                CP16(aDst + st + 16, Aro + (c + 2) * 32 + 8);
                CP16(bDst + st,      Bro + (c + 2) * 32);
                CP16(bDst + st + 16, Bro + (c + 2) * 32 + 8);
            }
            CPCOMMIT();
        }

        // compute chunk c
        {
            const uint32_t sA32 = smb + (uint32_t)(sc * STAGE_BYTES);
            const uint32_t sB32 = sA32 + OP_BYTES;
#pragma unroll
            for (int ks = 0; ks < 2; ks++) {
                const uint32_t kso = (uint32_t)(ks * 32);
                uint32_t b0[4], b1[4];
                ldmx4(b0, sB32 + bOff + kso);                               // n +0..15
                ldmx4(b1, sB32 + bOff + (uint32_t)(16 * PITCHB) + kso);     // n +16..31
#pragma unroll
                for (int i = 0; i < 4; i++) {
                    uint32_t a[4];
                    ldmx4(a, sA32 + aOff + (uint32_t)(i * 16 * PITCHB) + kso);
                    mma_16x8x16(acc[i][0], a, b0);
                    mma_16x8x16(acc[i][1], a, b0 + 2);
                    mma_16x8x16(acc[i][2], a, b1);
                    mma_16x8x16(acc[i][3], a, b1 + 2);
                }
            }
        }
        if (++sc == NSTAGE) sc = 0;
    }

    // ----------------------------- epilogue --------------------------------
    const float* Rz = RESID ? (R + (long)z * sR) : nullptr;
    float*  Cf = (float*)Cv  + (OUTH ? 0 : (long)z * sC);
    __half* Ch = (__half*)Cv + (OUTH ? (long)z * sC : 0);

#pragma unroll
    for (int i = 0; i < 4; i++) {
        const long r0 = m0 + warpM * 64 + i * 16 + g;
        const long r1 = r0 + 8;
#pragma unroll
        for (int j = 0; j < 4; j++) {
            const int cc = n0 + warpN * 32 + j * 8 + tg * 2;
            float2 v0, v1;
            v0.x = acc[i][j][0] * alpha; v0.y = acc[i][j][1] * alpha;
            v1.x = acc[i][j][2] * alpha; v1.y = acc[i][j][3] * alpha;
            if (BIAS) {
                const float2 bv = *(const float2*)(bias + cc);
                v0.x += bv.x; v0.y += bv.y;
                v1.x += bv.x; v1.y += bv.y;
            }
            if (RELU) {
                v0.x = fmaxf(v0.x, 0.0f); v0.y = fmaxf(v0.y, 0.0f);
                v1.x = fmaxf(v1.x, 0.0f); v1.y = fmaxf(v1.y, 0.0f);
            }
            if (RESID) {
                const float2 q0 = *(const float2*)(Rz + r0 * ldc + cc);
                const float2 q1 = *(const float2*)(Rz + r1 * ldc + cc);
                v0.x += q0.x; v0.y += q0.y;
                v1.x += q1.x; v1.y += q1.y;
            }
            if (OUTH) {
                *(__half2*)(Ch + r0 * ldc + cc) = __floats2half2_rn(v0.x, v0.y);
                *(__half2*)(Ch + r1 * ldc + cc) = __floats2half2_rn(v1.x, v1.y);
            } else {
                *(float2*)(Cf + r0 * ldc + cc) = v0;
                *(float2*)(Cf + r1 * ldc + cc) = v1;
            }
        }
    }
}

// ---------------------------------------------------------------------------
// Launch
// ---------------------------------------------------------------------------
extern "C" void kernel_launch(void* const* d_in, const int* /*in_sizes*/, int /*n_in*/,
                              void* d_out, int /*out_size*/)
{
    const float* x      = (const float*)d_in[0];
    const float* W_attn = (const float*)d_in[1];
    const float* b_attn = (const float*)d_in[2];
    const float* W_proj = (const float*)d_in[3];
    const float* b_proj = (const float*)d_in[4];
    const float* ln1_g  = (const float*)d_in[5];
    const float* ln1_b  = (const float*)d_in[6];
    const float* ln2_g  = (const float*)d_in[7];
    const float* ln2_b  = (const float*)d_in[8];
    const float* W1     = (const float*)d_in[9];
    const float* b1     = (const float*)d_in[10];
    const float* W2     = (const float*)d_in[11];
    const float* b2     = (const float*)d_in[12];
    float* out = (float*)d_out;

    __half *h16, *qkv16, *att16, *y16, *f16, *vt16, *wta, *wtp, *w1t, *w2t;
    float *att, *x1;
    cudaGetSymbolAddress((void**)&h16,   g_h16);
    cudaGetSymbolAddress((void**)&qkv16, g_qkv16);
    cudaGetSymbolAddress((void**)&att,   g_att);
    cudaGetSymbolAddress((void**)&att16, g_att16);
    cudaGetSymbolAddress((void**)&y16,   g_y16);
    cudaGetSymbolAddress((void**)&x1,    g_x1);
    cudaGetSymbolAddress((void**)&f16,   g_f16);
    cudaGetSymbolAddress((void**)&vt16,  g_vt16);
    cudaGetSymbolAddress((void**)&wta,   g_wta16);
    cudaGetSymbolAddress((void**)&wtp,   g_wtp16);
    cudaGetSymbolAddress((void**)&w1t,   g_w1t16);
    cudaGetSymbolAddress((void**)&w2t,   g_w2t16);

    cudaFuncSetAttribute(hgemm<true,  false, false, true >,
                         cudaFuncAttributeMaxDynamicSharedMemorySize, SMEM_DYN);
    cudaFuncSetAttribute(hgemm<false, false, false, false>,
                         cudaFuncAttributeMaxDynamicSharedMemorySize, SMEM_DYN);
    cudaFuncSetAttribute(hgemm<false, false, false, true >,
                         cudaFuncAttributeMaxDynamicSharedMemorySize, SMEM_DYN);
    cudaFuncSetAttribute(hgemm<true,  false, true,  false>,
                         cudaFuncAttributeMaxDynamicSharedMemorySize, SMEM_DYN);
    cudaFuncSetAttribute(hgemm<true,  true,  false, true >,
                         cudaFuncAttributeMaxDynamicSharedMemorySize, SMEM_DYN);

    const float inv_sqrt_c = 0.05103103630798287f;   // 1/sqrt(384)
    const long sQKV = (long)SEQ * (3 * EMB);
    const long sATT = (long)SEQ * SEQ;
    const dim3 tb(32, 8);

    // 0. weight transposes fp32 -> fp16: [K,N] -> [N,K]
    tr_w<<<dim3((3 * EMB) / 32, EMB / 32), tb>>>(W_attn, 3 * EMB, wta, EMB);
    tr_w<<<dim3(EMB / 32, EMB / 32),       tb>>>(W_proj, EMB,     wtp, EMB);
    tr_w<<<dim3((4 * EMB) / 32, EMB / 32), tb>>>(W1, 4 * EMB,     w1t, EMB);
    tr_w<<<dim3(EMB / 32, (4 * EMB) / 32), tb>>>(W2, EMB,         w2t, 4 * EMB);

    // 1. h = LN1(x)  (fp16)
    ln_kernel<<<MROWS, 128>>>(x, ln1_g, ln1_b, h16);

    // 2. qkv = h @ W_attn + b_attn   M=32768, N=1152, K=384  -> fp16
    hgemm<true, false, false, true><<<dim3(9, 256, 1), 256, SMEM_DYN>>>(
        h16, EMB, 0, wta, EMB, 0, b_attn, nullptr, 0,
        qkv16, 3 * EMB, 0, EMB, 1.0f);

    // 3. Vt[z] = V[z]^T  (fp16 [T,C] -> [C,T])
    tr_h<<<dim3(EMB / 32, SEQ / 32, BATCH), tb>>>(
        qkv16 + 2 * EMB, 3 * EMB, sQKV, vt16, SEQ, (long)EMB * SEQ);

    // 4. att = q @ k^T / sqrt(C)   M=N=256, K=384  -> fp32 logits
    hgemm<false, false, false, false><<<dim3(2, 2, BATCH), 256, SMEM_DYN>>>(
        qkv16, 3 * EMB, sQKV, qkv16 + EMB, 3 * EMB, sQKV, nullptr, nullptr, 0,
        att, SEQ, sATT, EMB, inv_sqrt_c);

    // 5. causal softmax -> fp16 probs
    softmax_causal<<<dim3(SEQ, BATCH), 256>>>(att, att16);

    // 6. y = att @ V (via Vt)   M=256, N=384, K=256  -> fp16
    hgemm<false, false, false, true><<<dim3(3, 2, BATCH), 256, SMEM_DYN>>>(
        att16, SEQ, sATT, vt16, SEQ, (long)EMB * SEQ, nullptr, nullptr, 0,
        y16, EMB, (long)SEQ * EMB, SEQ, 1.0f);

    // 7. x1 = x + y @ W_proj + b_proj   M=32768, N=384, K=384  -> fp32
    hgemm<true, false, true, false><<<dim3(3, 256, 1), 256, SMEM_DYN>>>(
        y16, EMB, 0, wtp, EMB, 0, b_proj, x, 0,
        x1, EMB, 0, EMB, 1.0f);

    // 8. h2 = LN2(x1)  (fp16, reuse h16)
    ln_kernel<<<MROWS, 128>>>(x1, ln2_g, ln2_b, h16);

    // 9. f = relu(h2 @ W1 + b1)   M=32768, N=1536, K=384  -> fp16
    hgemm<true, true, false, true><<<dim3(12, 256, 1), 256, SMEM_DYN>>>(
        h16, EMB, 0, w1t, EMB, 0, b1, nullptr, 0,
        f16, 4 * EMB, 0, EMB, 1.0f);

    // 10. out = x1 + f @ W2 + b2   M=32768, N=384, K=1536  -> fp32
    hgemm<true, false, true, false><<<dim3(3, 256, 1), 256, SMEM_DYN>>>(
        f16, 4 * EMB, 0, w2t, 4 * EMB, 0, b2, x1, 0,
        out, EMB, 0, 4 * EMB, 1.0f);
}

// round 14
// speedup vs baseline: 5.2766x; 1.0470x over previous
#include <cuda_runtime.h>
#include <cuda_fp16.h>
#include <math.h>
#include <stdint.h>

// ---------------------------------------------------------------------------
// TransformerBlock B=128, T=256, C=384 — fp16 mma.sync (m16n8k16) version.
// GEMM: 128x128 tile, 8 warps (2x4), warp 64x32, K chunks of 32, 3-stage
// cp.async pipeline, ldmatrix fragments, fused epilogue, fp32 accumulate.
// This round: merged weight-transpose kernel, warp-per-row LN & softmax,
// causal tile skip (QK) and causal K-trim (S@V).
// ---------------------------------------------------------------------------

#define BATCH 128
#define SEQ   256
#define EMB   384
#define MROWS (BATCH * SEQ)   // 32768

#define PITCHB     80                      // smem row pitch bytes (64B data + 16 pad)
#define OP_BYTES   (128 * PITCHB)          // 10240 per operand per stage
#define STAGE_BYTES (2 * OP_BYTES)         // 20480
#define NSTAGE     3
#define SMEM_DYN   (NSTAGE * STAGE_BYTES)  // 61440

// --------------------------- device scratch --------------------------------
__device__ __half g_h16  [(size_t)MROWS * EMB];          // LN1/LN2 out (fp16)
__device__ __half g_qkv16[(size_t)MROWS * 3 * EMB];
__device__ float  g_att  [(size_t)BATCH * SEQ * SEQ];    // logits (fp32)
__device__ __half g_att16[(size_t)BATCH * SEQ * SEQ];    // softmax probs (fp16)
__device__ __half g_y16  [(size_t)MROWS * EMB];
__device__ float  g_x1   [(size_t)MROWS * EMB];
__device__ __half g_f16  [(size_t)MROWS * 4 * EMB];
__device__ __half g_vt16 [(size_t)BATCH * EMB * SEQ];    // V^T per batch [C,T]
__device__ __half g_wta16[(size_t)(3 * EMB) * EMB];
__device__ __half g_wtp16[(size_t)EMB * EMB];
__device__ __half g_w1t16[(size_t)(4 * EMB) * EMB];
__device__ __half g_w2t16[(size_t)EMB * (4 * EMB)];

// ----------------------------- PTX helpers ---------------------------------
__device__ __forceinline__ void mma_16x8x16(float* d, const uint32_t* a, const uint32_t* b) {
    asm volatile(
        "mma.sync.aligned.m16n8k16.row.col.f32.f16.f16.f32 "
        "{%0,%1,%2,%3}, {%4,%5,%6,%7}, {%8,%9}, {%0,%1,%2,%3};"
        : "+f"(d[0]), "+f"(d[1]), "+f"(d[2]), "+f"(d[3])
        : "r"(a[0]), "r"(a[1]), "r"(a[2]), "r"(a[3]), "r"(b[0]), "r"(b[1]));
}

__device__ __forceinline__ void ldmx4(uint32_t* d, uint32_t addr) {
    asm volatile(
        "ldmatrix.sync.aligned.m8n8.x4.shared.b16 {%0,%1,%2,%3}, [%4];"
        : "=r"(d[0]), "=r"(d[1]), "=r"(d[2]), "=r"(d[3]) : "r"(addr));
}

#define CP16(dst, src) \
    asm volatile("cp.async.cg.shared.global [%0], [%1], 16;" :: "r"(dst), "l"(src))
#define CPCOMMIT() asm volatile("cp.async.commit_group;")
#define CPWAIT1()  asm volatile("cp.async.wait_group 1;")

// ---------------------------------------------------------------------------
// LayerNorm, warp-per-row: block 128 = 4 warps = 4 rows, grid MROWS/4.
// Each lane owns 12 contiguous cols (3x float4). No __syncthreads.
// ---------------------------------------------------------------------------
__global__ __launch_bounds__(128)
void ln_kernel(const float* __restrict__ x, const float* __restrict__ g,
               const float* __restrict__ b, __half* __restrict__ out)
{
    const int lane = threadIdx.x & 31;
    const long row = (long)blockIdx.x * 4 + (threadIdx.x >> 5);
    const float* xr = x + row * EMB + lane * 12;

    float4 v0 = *(const float4*)(xr);
    float4 v1 = *(const float4*)(xr + 4);
    float4 v2 = *(const float4*)(xr + 8);

    float s = v0.x + v0.y + v0.z + v0.w + v1.x + v1.y + v1.z + v1.w
            + v2.x + v2.y + v2.z + v2.w;
    float q = v0.x * v0.x + v0.y * v0.y + v0.z * v0.z + v0.w * v0.w
            + v1.x * v1.x + v1.y * v1.y + v1.z * v1.z + v1.w * v1.w
            + v2.x * v2.x + v2.y * v2.y + v2.z * v2.z + v2.w * v2.w;
#pragma unroll
    for (int o = 16; o; o >>= 1) {
        s += __shfl_xor_sync(0xffffffffu, s, o);
        q += __shfl_xor_sync(0xffffffffu, q, o);
    }
    const float mu  = s * (1.0f / EMB);
    const float var = q * (1.0f / EMB) - mu * mu;
    const float inv = rsqrtf(var + 1e-5f);

    const float* gr = g + lane * 12;
    const float* br = b + lane * 12;
    __half* orow = out + row * EMB + lane * 12;
    float vv[12] = {v0.x, v0.y, v0.z, v0.w, v1.x, v1.y, v1.z, v1.w,
                    v2.x, v2.y, v2.z, v2.w};
#pragma unroll
    for (int j = 0; j < 12; j += 2) {
        float a0 = (vv[j]     - mu) * inv * gr[j]     + br[j];
        float a1 = (vv[j + 1] - mu) * inv * gr[j + 1] + br[j + 1];
        *(__half2*)(orow + j) = __floats2half2_rn(a0, a1);
    }
}

// ---------------------------------------------------------------------------
// Causal softmax, warp-per-row: block 128 = 4 rows, grid MROWS/4.
// Lane owns 8 contiguous cols. fp32 logits in, fp16 probs out (masked -> 0).
// ---------------------------------------------------------------------------
__global__ __launch_bounds__(128)
void softmax_causal(const float* __restrict__ att, __half* __restrict__ outp)
{
    const int lane = threadIdx.x & 31;
    const long row = (long)blockIdx.x * 4 + (threadIdx.x >> 5);
    const int t = (int)(row & (SEQ - 1));
    const long off = row * SEQ;
    const int c0 = lane * 8;

    float4 u0 = *(const float4*)(att + off + c0);
    float4 u1 = *(const float4*)(att + off + c0 + 4);
    float v[8] = {u0.x, u0.y, u0.z, u0.w, u1.x, u1.y, u1.z, u1.w};
#pragma unroll
    for (int j = 0; j < 8; j++)
        if (c0 + j > t) v[j] = -1e30f;

    float m = v[0];
#pragma unroll
    for (int j = 1; j < 8; j++) m = fmaxf(m, v[j]);
#pragma unroll
    for (int o = 16; o; o >>= 1) m = fmaxf(m, __shfl_xor_sync(0xffffffffu, m, o));

    float e[8], s = 0.0f;
#pragma unroll
    for (int j = 0; j < 8; j++) {
        e[j] = (c0 + j <= t) ? expf(v[j] - m) : 0.0f;
        s += e[j];
    }
#pragma unroll
    for (int o = 16; o; o >>= 1) s += __shfl_xor_sync(0xffffffffu, s, o);
    const float inv = 1.0f / s;

    __half h[8];
#pragma unroll
    for (int j = 0; j < 8; j++) h[j] = __float2half(e[j] * inv);
    *(uint4*)(outp + off + c0) = *(uint4*)h;
}

// ---------------------------------------------------------------------------
// Merged weight transpose fp32 -> fp16 for all four weights, one launch.
// 1728 flat blocks, block (32,8).
// ---------------------------------------------------------------------------
__global__ __launch_bounds__(256)
void tr_all(const float* __restrict__ Wa, const float* __restrict__ Wp,
            const float* __restrict__ Wm1, const float* __restrict__ Wm2,
            __half* __restrict__ wta, __half* __restrict__ wtp,
            __half* __restrict__ w1t, __half* __restrict__ w2t)
{
    __shared__ float t[32][33];
    int f = blockIdx.x;
    const float* in; __half* out; int ldi, ldo, bx, by;
    if (f < 432)       {            bx = f % 36; by = f / 36; in = Wa;  out = wta; ldi = 1152; ldo = 384; }
    else if (f < 576)  { f -= 432;  bx = f % 12; by = f / 12; in = Wp;  out = wtp; ldi = 384;  ldo = 384; }
    else if (f < 1152) { f -= 576;  bx = f % 48; by = f / 48; in = Wm1; out = w1t; ldi = 1536; ldo = 384; }
    else               { f -= 1152; bx = f % 12; by = f / 12; in = Wm2; out = w2t; ldi = 384;  ldo = 1536; }

    const int r0 = by * 32, c0 = bx * 32;
    const int tx = threadIdx.x, ty = threadIdx.y;
#pragma unroll
    for (int i = ty; i < 32; i += 8)
        t[i][tx] = in[(long)(r0 + i) * ldi + c0 + tx];
    __syncthreads();
#pragma unroll
    for (int i = ty; i < 32; i += 8)
        out[(long)(c0 + i) * ldo + r0 + tx] = __float2half(t[tx][i]);
}

// ---------------------------------------------------------------------------
// Transpose fp16 -> fp16 (batched):  out[z][c][r] = in[z][r][c]
// ---------------------------------------------------------------------------
__global__ __launch_bounds__(256)
void tr_h(const __half* __restrict__ in, int ldi, long sI,
          __half* __restrict__ out, int ldo, long sO)
{
    __shared__ __half t[32][34];
    const __half* I = in + (long)blockIdx.z * sI;
    __half*       O = out + (long)blockIdx.z * sO;
    const int r0 = blockIdx.y * 32, c0 = blockIdx.x * 32;
    const int tx = threadIdx.x, ty = threadIdx.y;
#pragma unroll
    for (int i = ty; i < 32; i += 8)
        t[i][tx] = I[(long)(r0 + i) * ldi + c0 + tx];
    __syncthreads();
#pragma unroll
    for (int i = ty; i < 32; i += 8)
        O[(long)(c0 + i) * ldo + r0 + tx] = t[tx][i];
}

// ---------------------------------------------------------------------------
// fp16 tensor-core NT GEMM:  C[z] = epi( alpha * A[z] @ Bt[z]^T )
//   A  [M,K] fp16 row-major (lda halves, batch stride sA)
//   Bt [N,K] fp16 row-major (ldb halves, batch stride sB)
// 128x128 tile, K chunks of 32, 3-stage cp.async pipeline.
// causal: 0 = none; 1 = skip tiles entirely above the diagonal (QK);
//         2 = trim K to m0+128 (S@V — probs beyond the diagonal are zero).
// ---------------------------------------------------------------------------
template<bool BIAS, bool RELU, bool RESID, bool OUTH>
__global__ __launch_bounds__(256, 2)
void hgemm(const __half* __restrict__ A, int lda, long sA,
           const __half* __restrict__ Bt, int ldb, long sB,
           const float* __restrict__ bias,
           const float* __restrict__ R, long sR,
           void* __restrict__ Cv, int ldc, long sC,
           int K, float alpha, int causal)
{
    extern __shared__ __align__(16) char smem[];
    const uint32_t smb = (uint32_t)__cvta_generic_to_shared(smem);

    const int tid  = threadIdx.x;
    const int lane = tid & 31;
    const int wid  = tid >> 5;
    const int warpM = wid >> 2;      // 0..1 -> 64-row half
    const int warpN = wid & 3;       // 0..3 -> 32-col quarter
    const int g  = lane >> 2;        // 0..7
    const int tg = lane & 3;         // 0..3

    const int  z  = blockIdx.z;
    const long m0 = (long)blockIdx.y * 128;
    const int  n0 = blockIdx.x * 128;

    if (causal == 1 && n0 > (int)m0 + 127) return;      // fully-masked QK tile
    if (causal == 2) K = min(K, (int)m0 + 128);          // zero probs beyond diag

    const __half* Az = A  + (long)z * sA + m0 * lda;
    const __half* Bz = Bt + (long)z * sB + (long)n0 * ldb;

    // loader: thread -> (row = tid>>1, 32B half-row = (tid&1))
    const int rL = tid >> 1;
    const int qb = (tid & 1) * 2;                 // 16B-quarter base (0 or 2)
    const __half* Aro = Az + (long)rL * lda + qb * 8;
    const __half* Bro = Bz + (long)rL * ldb + qb * 8;
    const uint32_t aDst = smb + (uint32_t)(rL * PITCHB + qb * 16);
    const uint32_t bDst = aDst + OP_BYTES;

    // ldmatrix per-lane fragment offsets (bytes within operand tile)
    const uint32_t aOff =
        (uint32_t)((warpM * 64 + (lane & 7) + ((lane >> 3) & 1) * 8) * PITCHB
                   + ((lane >> 4) & 1) * 16);
    const uint32_t bOff =
        (uint32_t)((warpN * 32 + (lane & 7) + ((lane >> 4) & 1) * 8) * PITCHB
                   + ((lane >> 3) & 1) * 16);

    float acc[4][4][4];
#pragma unroll
    for (int i = 0; i < 4; i++)
#pragma unroll
        for (int j = 0; j < 4; j++)
#pragma unroll
            for (int r = 0; r < 4; r++) acc[i][j][r] = 0.0f;

    const int nc = K >> 5;

    // prologue: chunks 0 and 1
#pragma unroll
    for (int c = 0; c < 2; c++) {
        const uint32_t st = (uint32_t)(c * STAGE_BYTES);
        CP16(aDst + st,      Aro + c * 32);
        CP16(aDst + st + 16, Aro + c * 32 + 8);
        CP16(bDst + st,      Bro + c * 32);
        CP16(bDst + st + 16, Bro + c * 32 + 8);
        CPCOMMIT();
    }

    int sc = 0;                 // stage of chunk c
    for (int c = 0; c < nc; c++) {
        CPWAIT1();              // chunk c resident
        __syncthreads();        // all warps done with stage (c-1)%3 compute

        // issue chunk c+2 into stage (c+2)%3  (== (c-1)%3, now free)
        {
            int s2 = sc + 2; if (s2 >= NSTAGE) s2 -= NSTAGE;
            const uint32_t st = (uint32_t)(s2 * STAGE_BYTES);
            if (c + 2 < nc) {
                CP16(aDst + st,      Aro + (c + 2) * 32);
                CP16(aDst + st + 16, Aro + (c + 2) * 32 + 8);
                CP16(bDst + st,      Bro + (c + 2) * 32);
                CP16(bDst + st + 16, Bro + (c + 2) * 32 + 8);
            }
            CPCOMMIT();
        }

        // compute chunk c
        {
            const uint32_t sA32 = smb + (uint32_t)(sc * STAGE_BYTES);
            const uint32_t sB32 = sA32 + OP_BYTES;
#pragma unroll
            for (int ks = 0; ks < 2; ks++) {
                const uint32_t kso = (uint32_t)(ks * 32);
                uint32_t b0[4], b1[4];
                ldmx4(b0, sB32 + bOff + kso);                               // n +0..15
                ldmx4(b1, sB32 + bOff + (uint32_t)(16 * PITCHB) + kso);     // n +16..31
#pragma unroll
                for (int i = 0; i < 4; i++) {
                    uint32_t a[4];
                    ldmx4(a, sA32 + aOff + (uint32_t)(i * 16 * PITCHB) + kso);
                    mma_16x8x16(acc[i][0], a, b0);
                    mma_16x8x16(acc[i][1], a, b0 + 2);
                    mma_16x8x16(acc[i][2], a, b1);
                    mma_16x8x16(acc[i][3], a, b1 + 2);
                }
            }
        }
        if (++sc == NSTAGE) sc = 0;
    }

    // ----------------------------- epilogue --------------------------------
    const float* Rz = RESID ? (R + (long)z * sR) : nullptr;
    float*  Cf = (float*)Cv  + (OUTH ? 0 : (long)z * sC);
    __half* Ch = (__half*)Cv + (OUTH ? (long)z * sC : 0);

#pragma unroll
    for (int i = 0; i < 4; i++) {
        const long r0 = m0 + warpM * 64 + i * 16 + g;
        const long r1 = r0 + 8;
#pragma unroll
        for (int j = 0; j < 4; j++) {
            const int cc = n0 + warpN * 32 + j * 8 + tg * 2;
            float2 v0, v1;
            v0.x = acc[i][j][0] * alpha; v0.y = acc[i][j][1] * alpha;
            v1.x = acc[i][j][2] * alpha; v1.y = acc[i][j][3] * alpha;
            if (BIAS) {
                const float2 bv = *(const float2*)(bias + cc);
                v0.x += bv.x; v0.y += bv.y;
                v1.x += bv.x; v1.y += bv.y;
            }
            if (RELU) {
                v0.x = fmaxf(v0.x, 0.0f); v0.y = fmaxf(v0.y, 0.0f);
                v1.x = fmaxf(v1.x, 0.0f); v1.y = fmaxf(v1.y, 0.0f);
            }
            if (RESID) {
                const float2 q0 = *(const float2*)(Rz + r0 * ldc + cc);
                const float2 q1 = *(const float2*)(Rz + r1 * ldc + cc);
                v0.x += q0.x; v0.y += q0.y;
                v1.x += q1.x; v1.y += q1.y;
            }
            if (OUTH) {
                *(__half2*)(Ch + r0 * ldc + cc) = __floats2half2_rn(v0.x, v0.y);
                *(__half2*)(Ch + r1 * ldc + cc) = __floats2half2_rn(v1.x, v1.y);
            } else {
                *(float2*)(Cf + r0 * ldc + cc) = v0;
                *(float2*)(Cf + r1 * ldc + cc) = v1;
            }
        }
    }
}

// ---------------------------------------------------------------------------
// Launch
// ---------------------------------------------------------------------------
extern "C" void kernel_launch(void* const* d_in, const int* /*in_sizes*/, int /*n_in*/,
                              void* d_out, int /*out_size*/)
{
    const float* x      = (const float*)d_in[0];
    const float* W_attn = (const float*)d_in[1];
    const float* b_attn = (const float*)d_in[2];
    const float* W_proj = (const float*)d_in[3];
    const float* b_proj = (const float*)d_in[4];
    const float* ln1_g  = (const float*)d_in[5];
    const float* ln1_b  = (const float*)d_in[6];
    const float* ln2_g  = (const float*)d_in[7];
    const float* ln2_b  = (const float*)d_in[8];
    const float* W1     = (const float*)d_in[9];
    const float* b1     = (const float*)d_in[10];
    const float* W2     = (const float*)d_in[11];
    const float* b2     = (const float*)d_in[12];
    float* out = (float*)d_out;

    __half *h16, *qkv16, *att16, *y16, *f16, *vt16, *wta, *wtp, *w1t, *w2t;
    float *att, *x1;
    cudaGetSymbolAddress((void**)&h16,   g_h16);
    cudaGetSymbolAddress((void**)&qkv16, g_qkv16);
    cudaGetSymbolAddress((void**)&att,   g_att);
    cudaGetSymbolAddress((void**)&att16, g_att16);
    cudaGetSymbolAddress((void**)&y16,   g_y16);
    cudaGetSymbolAddress((void**)&x1,    g_x1);
    cudaGetSymbolAddress((void**)&f16,   g_f16);
    cudaGetSymbolAddress((void**)&vt16,  g_vt16);
    cudaGetSymbolAddress((void**)&wta,   g_wta16);
    cudaGetSymbolAddress((void**)&wtp,   g_wtp16);
    cudaGetSymbolAddress((void**)&w1t,   g_w1t16);
    cudaGetSymbolAddress((void**)&w2t,   g_w2t16);

    cudaFuncSetAttribute(hgemm<true,  false, false, true >,
                         cudaFuncAttributeMaxDynamicSharedMemorySize, SMEM_DYN);
    cudaFuncSetAttribute(hgemm<false, false, false, false>,
                         cudaFuncAttributeMaxDynamicSharedMemorySize, SMEM_DYN);
    cudaFuncSetAttribute(hgemm<false, false, false, true >,
                         cudaFuncAttributeMaxDynamicSharedMemorySize, SMEM_DYN);
    cudaFuncSetAttribute(hgemm<true,  false, true,  false>,
                         cudaFuncAttributeMaxDynamicSharedMemorySize, SMEM_DYN);
    cudaFuncSetAttribute(hgemm<true,  true,  false, true >,
                         cudaFuncAttributeMaxDynamicSharedMemorySize, SMEM_DYN);

    const float inv_sqrt_c = 0.05103103630798287f;   // 1/sqrt(384)
    const long sQKV = (long)SEQ * (3 * EMB);
    const long sATT = (long)SEQ * SEQ;
    const dim3 tb(32, 8);

    // 0. all weight transposes in one launch (fp32 -> fp16, [K,N] -> [N,K])
    tr_all<<<1728, tb>>>(W_attn, W_proj, W1, W2, wta, wtp, w1t, w2t);

    // 1. h = LN1(x)  (fp16, warp-per-row)
    ln_kernel<<<MROWS / 4, 128>>>(x, ln1_g, ln1_b, h16);

    // 2. qkv = h @ W_attn + b_attn   M=32768, N=1152, K=384  -> fp16
    hgemm<true, false, false, true><<<dim3(9, 256, 1), 256, SMEM_DYN>>>(
        h16, EMB, 0, wta, EMB, 0, b_attn, nullptr, 0,
        qkv16, 3 * EMB, 0, EMB, 1.0f, 0);

    // 3. Vt[z] = V[z]^T  (fp16 [T,C] -> [C,T])
    tr_h<<<dim3(EMB / 32, SEQ / 32, BATCH), tb>>>(
        qkv16 + 2 * EMB, 3 * EMB, sQKV, vt16, SEQ, (long)EMB * SEQ);

    // 4. att = q @ k^T / sqrt(C)   M=N=256, K=384  -> fp32 logits
    //    (causal=1: the all-masked upper tile is skipped, never read)
    hgemm<false, false, false, false><<<dim3(2, 2, BATCH), 256, SMEM_DYN>>>(
        qkv16, 3 * EMB, sQKV, qkv16 + EMB, 3 * EMB, sQKV, nullptr, nullptr, 0,
        att, SEQ, sATT, EMB, inv_sqrt_c, 1);

    // 5. causal softmax -> fp16 probs (warp-per-row)
    softmax_causal<<<MROWS / 4, 128>>>(att, att16);

    // 6. y = att @ V (via Vt)   M=256, N=384, K=256  -> fp16
    //    (causal=2: rows < 128 only need K=128)
    hgemm<false, false, false, true><<<dim3(3, 2, BATCH), 256, SMEM_DYN>>>(
        att16, SEQ, sATT, vt16, SEQ, (long)EMB * SEQ, nullptr, nullptr, 0,
        y16, EMB, (long)SEQ * EMB, SEQ, 1.0f, 2);

    // 7. x1 = x + y @ W_proj + b_proj   M=32768, N=384, K=384  -> fp32
    hgemm<true, false, true, false><<<dim3(3, 256, 1), 256, SMEM_DYN>>>(
        y16, EMB, 0, wtp, EMB, 0, b_proj, x, 0,
        x1, EMB, 0, EMB, 1.0f, 0);

    // 8. h2 = LN2(x1)  (fp16, reuse h16)
    ln_kernel<<<MROWS / 4, 128>>>(x1, ln2_g, ln2_b, h16);

    // 9. f = relu(h2 @ W1 + b1)   M=32768, N=1536, K=384  -> fp16
    hgemm<true, true, false, true><<<dim3(12, 256, 1), 256, SMEM_DYN>>>(
        h16, EMB, 0, w1t, EMB, 0, b1, nullptr, 0,
        f16, 4 * EMB, 0, EMB, 1.0f, 0);

    // 10. out = x1 + f @ W2 + b2   M=32768, N=384, K=1536  -> fp32
    hgemm<true, false, true, false><<<dim3(3, 256, 1), 256, SMEM_DYN>>>(
        f16, 4 * EMB, 0, w2t, 4 * EMB, 0, b2, x1, 0,
        out, EMB, 0, 4 * EMB, 1.0f, 0);
}

// round 15
// speedup vs baseline: 5.4550x; 1.0338x over previous
#include <cuda_runtime.h>
#include <cuda_fp16.h>
#include <math.h>
#include <stdint.h>

// ---------------------------------------------------------------------------
// TransformerBlock B=128, T=256, C=384 — fp16 mma.sync (m16n8k16) version.
// GEMM: 128x128 tile, 8 warps (2x4), warp 64x32, K chunks of 32, 3-stage
// cp.async pipeline, ldmatrix fragments, fused epilogue, fp32 accumulate.
// This round: V^T is produced directly by the QKV GEMM epilogue (SMEM bounce,
// coalesced transposed store) — the separate 48MB-round-trip tr_h kernel is
// gone. Warp-per-row LN & softmax; causal tile skip (QK) / K-trim (S@V).
// ---------------------------------------------------------------------------

#define BATCH 128
#define SEQ   256
#define EMB   384
#define MROWS (BATCH * SEQ)   // 32768

#define PITCHB     80                      // smem row pitch bytes (64B data + 16 pad)
#define OP_BYTES   (128 * PITCHB)          // 10240 per operand per stage
#define STAGE_BYTES (2 * OP_BYTES)         // 20480
#define NSTAGE     3
#define SMEM_DYN   (NSTAGE * STAGE_BYTES)  // 61440  (>= 128*136*2 = 34816 for VT bounce)
#define VTP        136                     // transpose-bounce pitch (halves)

// --------------------------- device scratch --------------------------------
__device__ __half g_h16  [(size_t)MROWS * EMB];          // LN1/LN2 out (fp16)
__device__ __half g_qkv16[(size_t)MROWS * 3 * EMB];      // Q,K used; V region unused
__device__ float  g_att  [(size_t)BATCH * SEQ * SEQ];    // logits (fp32)
__device__ __half g_att16[(size_t)BATCH * SEQ * SEQ];    // softmax probs (fp16)
__device__ __half g_y16  [(size_t)MROWS * EMB];
__device__ float  g_x1   [(size_t)MROWS * EMB];
__device__ __half g_f16  [(size_t)MROWS * 4 * EMB];
__device__ __half g_vt16 [(size_t)BATCH * EMB * SEQ];    // V^T per batch [C,T]
__device__ __half g_wta16[(size_t)(3 * EMB) * EMB];
__device__ __half g_wtp16[(size_t)EMB * EMB];
__device__ __half g_w1t16[(size_t)(4 * EMB) * EMB];
__device__ __half g_w2t16[(size_t)EMB * (4 * EMB)];

// ----------------------------- PTX helpers ---------------------------------
__device__ __forceinline__ void mma_16x8x16(float* d, const uint32_t* a, const uint32_t* b) {
    asm volatile(
        "mma.sync.aligned.m16n8k16.row.col.f32.f16.f16.f32 "
        "{%0,%1,%2,%3}, {%4,%5,%6,%7}, {%8,%9}, {%0,%1,%2,%3};"
        : "+f"(d[0]), "+f"(d[1]), "+f"(d[2]), "+f"(d[3])
        : "r"(a[0]), "r"(a[1]), "r"(a[2]), "r"(a[3]), "r"(b[0]), "r"(b[1]));
}

__device__ __forceinline__ void ldmx4(uint32_t* d, uint32_t addr) {
    asm volatile(
        "ldmatrix.sync.aligned.m8n8.x4.shared.b16 {%0,%1,%2,%3}, [%4];"
        : "=r"(d[0]), "=r"(d[1]), "=r"(d[2]), "=r"(d[3]) : "r"(addr));
}

#define CP16(dst, src) \
    asm volatile("cp.async.cg.shared.global [%0], [%1], 16;" :: "r"(dst), "l"(src))
#define CPCOMMIT() asm volatile("cp.async.commit_group;")
#define CPWAIT1()  asm volatile("cp.async.wait_group 1;")

// ---------------------------------------------------------------------------
// LayerNorm, warp-per-row: block 128 = 4 warps = 4 rows, grid MROWS/4.
// ---------------------------------------------------------------------------
__global__ __launch_bounds__(128)
void ln_kernel(const float* __restrict__ x, const float* __restrict__ g,
               const float* __restrict__ b, __half* __restrict__ out)
{
    const int lane = threadIdx.x & 31;
    const long row = (long)blockIdx.x * 4 + (threadIdx.x >> 5);
    const float* xr = x + row * EMB + lane * 12;

    float4 v0 = *(const float4*)(xr);
    float4 v1 = *(const float4*)(xr + 4);
    float4 v2 = *(const float4*)(xr + 8);

    float s = v0.x + v0.y + v0.z + v0.w + v1.x + v1.y + v1.z + v1.w
            + v2.x + v2.y + v2.z + v2.w;
    float q = v0.x * v0.x + v0.y * v0.y + v0.z * v0.z + v0.w * v0.w
            + v1.x * v1.x + v1.y * v1.y + v1.z * v1.z + v1.w * v1.w
            + v2.x * v2.x + v2.y * v2.y + v2.z * v2.z + v2.w * v2.w;
#pragma unroll
    for (int o = 16; o; o >>= 1) {
        s += __shfl_xor_sync(0xffffffffu, s, o);
        q += __shfl_xor_sync(0xffffffffu, q, o);
    }
    const float mu  = s * (1.0f / EMB);
    const float var = q * (1.0f / EMB) - mu * mu;
    const float inv = rsqrtf(var + 1e-5f);

    const float* gr = g + lane * 12;
    const float* br = b + lane * 12;
    __half* orow = out + row * EMB + lane * 12;
    float vv[12] = {v0.x, v0.y, v0.z, v0.w, v1.x, v1.y, v1.z, v1.w,
                    v2.x, v2.y, v2.z, v2.w};
#pragma unroll
    for (int j = 0; j < 12; j += 2) {
        float a0 = (vv[j]     - mu) * inv * gr[j]     + br[j];
        float a1 = (vv[j + 1] - mu) * inv * gr[j + 1] + br[j + 1];
        *(__half2*)(orow + j) = __floats2half2_rn(a0, a1);
    }
}

// ---------------------------------------------------------------------------
// Causal softmax, warp-per-row: fp32 logits in, fp16 probs out (masked -> 0).
// ---------------------------------------------------------------------------
__global__ __launch_bounds__(128)
void softmax_causal(const float* __restrict__ att, __half* __restrict__ outp)
{
    const int lane = threadIdx.x & 31;
    const long row = (long)blockIdx.x * 4 + (threadIdx.x >> 5);
    const int t = (int)(row & (SEQ - 1));
    const long off = row * SEQ;
    const int c0 = lane * 8;

    float4 u0 = *(const float4*)(att + off + c0);
    float4 u1 = *(const float4*)(att + off + c0 + 4);
    float v[8] = {u0.x, u0.y, u0.z, u0.w, u1.x, u1.y, u1.z, u1.w};
#pragma unroll
    for (int j = 0; j < 8; j++)
        if (c0 + j > t) v[j] = -1e30f;

    float m = v[0];
#pragma unroll
    for (int j = 1; j < 8; j++) m = fmaxf(m, v[j]);
#pragma unroll
    for (int o = 16; o; o >>= 1) m = fmaxf(m, __shfl_xor_sync(0xffffffffu, m, o));

    float e[8], s = 0.0f;
#pragma unroll
    for (int j = 0; j < 8; j++) {
        e[j] = (c0 + j <= t) ? expf(v[j] - m) : 0.0f;
        s += e[j];
    }
#pragma unroll
    for (int o = 16; o; o >>= 1) s += __shfl_xor_sync(0xffffffffu, s, o);
    const float inv = 1.0f / s;

    __half h[8];
#pragma unroll
    for (int j = 0; j < 8; j++) h[j] = __float2half(e[j] * inv);
    *(uint4*)(outp + off + c0) = *(uint4*)h;
}

// ---------------------------------------------------------------------------
// Merged weight transpose fp32 -> fp16 for all four weights, one launch.
// ---------------------------------------------------------------------------
__global__ __launch_bounds__(256)
void tr_all(const float* __restrict__ Wa, const float* __restrict__ Wp,
            const float* __restrict__ Wm1, const float* __restrict__ Wm2,
            __half* __restrict__ wta, __half* __restrict__ wtp,
            __half* __restrict__ w1t, __half* __restrict__ w2t)
{
    __shared__ float t[32][33];
    int f = blockIdx.x;
    const float* in; __half* out; int ldi, ldo, bx, by;
    if (f < 432)       {            bx = f % 36; by = f / 36; in = Wa;  out = wta; ldi = 1152; ldo = 384; }
    else if (f < 576)  { f -= 432;  bx = f % 12; by = f / 12; in = Wp;  out = wtp; ldi = 384;  ldo = 384; }
    else if (f < 1152) { f -= 576;  bx = f % 48; by = f / 48; in = Wm1; out = w1t; ldi = 1536; ldo = 384; }
    else               { f -= 1152; bx = f % 12; by = f / 12; in = Wm2; out = w2t; ldi = 384;  ldo = 1536; }

    const int r0 = by * 32, c0 = bx * 32;
    const int tx = threadIdx.x, ty = threadIdx.y;
#pragma unroll
    for (int i = ty; i < 32; i += 8)
        t[i][tx] = in[(long)(r0 + i) * ldi + c0 + tx];
    __syncthreads();
#pragma unroll
    for (int i = ty; i < 32; i += 8)
        out[(long)(c0 + i) * ldo + r0 + tx] = __float2half(t[tx][i]);
}

// ---------------------------------------------------------------------------
// fp16 tensor-core NT GEMM:  C[z] = epi( alpha * A[z] @ Bt[z]^T )
// causal: 0 none; 1 skip fully-masked QK tiles; 2 trim K to m0+128 (S@V).
// VTR: tiles with n0 >= 768 are written TRANSPOSED (bias applied) into
//      vt[z][c][t] via an SMEM bounce — produces V^T for free in QKV GEMM.
// ---------------------------------------------------------------------------
template<bool BIAS, bool RELU, bool RESID, bool OUTH, bool VTR>
__global__ __launch_bounds__(256, 2)
void hgemm(const __half* __restrict__ A, int lda, long sA,
           const __half* __restrict__ Bt, int ldb, long sB,
           const float* __restrict__ bias,
           const float* __restrict__ R, long sR,
           void* __restrict__ Cv, int ldc, long sC,
           int K, float alpha, int causal, __half* __restrict__ vt)
{
    extern __shared__ __align__(16) char smem[];
    const uint32_t smb = (uint32_t)__cvta_generic_to_shared(smem);

    const int tid  = threadIdx.x;
    const int lane = tid & 31;
    const int wid  = tid >> 5;
    const int warpM = wid >> 2;      // 0..1 -> 64-row half
    const int warpN = wid & 3;       // 0..3 -> 32-col quarter
    const int g  = lane >> 2;        // 0..7
    const int tg = lane & 3;         // 0..3

    const int  z  = blockIdx.z;
    const long m0 = (long)blockIdx.y * 128;
    const int  n0 = blockIdx.x * 128;

    if (causal == 1 && n0 > (int)m0 + 127) return;      // fully-masked QK tile
    if (causal == 2) K = min(K, (int)m0 + 128);          // zero probs beyond diag

    const __half* Az = A  + (long)z * sA + m0 * lda;
    const __half* Bz = Bt + (long)z * sB + (long)n0 * ldb;

    // loader: thread -> (row = tid>>1, 32B half-row = (tid&1))
    const int rL = tid >> 1;
    const int qb = (tid & 1) * 2;                 // 16B-quarter base (0 or 2)
    const __half* Aro = Az + (long)rL * lda + qb * 8;
    const __half* Bro = Bz + (long)rL * ldb + qb * 8;
    const uint32_t aDst = smb + (uint32_t)(rL * PITCHB + qb * 16);
    const uint32_t bDst = aDst + OP_BYTES;

    // ldmatrix per-lane fragment offsets (bytes within operand tile)
    const uint32_t aOff =
        (uint32_t)((warpM * 64 + (lane & 7) + ((lane >> 3) & 1) * 8) * PITCHB
                   + ((lane >> 4) & 1) * 16);
    const uint32_t bOff =
        (uint32_t)((warpN * 32 + (lane & 7) + ((lane >> 4) & 1) * 8) * PITCHB
                   + ((lane >> 3) & 1) * 16);

    float acc[4][4][4];
#pragma unroll
    for (int i = 0; i < 4; i++)
#pragma unroll
        for (int j = 0; j < 4; j++)
#pragma unroll
            for (int r = 0; r < 4; r++) acc[i][j][r] = 0.0f;

    const int nc = K >> 5;

    // prologue: chunks 0 and 1
#pragma unroll
    for (int c = 0; c < 2; c++) {
        const uint32_t st = (uint32_t)(c * STAGE_BYTES);
        CP16(aDst + st,      Aro + c * 32);
        CP16(aDst + st + 16, Aro + c * 32 + 8);
        CP16(bDst + st,      Bro + c * 32);
        CP16(bDst + st + 16, Bro + c * 32 + 8);
        CPCOMMIT();
    }

    int sc = 0;                 // stage of chunk c
    for (int c = 0; c < nc; c++) {
        CPWAIT1();              // chunk c resident
        __syncthreads();        // all warps done with stage (c-1)%3 compute

        // issue chunk c+2 into stage (c+2)%3  (== (c-1)%3, now free)
        {
            int s2 = sc + 2; if (s2 >= NSTAGE) s2 -= NSTAGE;
            const uint32_t st = (uint32_t)(s2 * STAGE_BYTES);
            if (c + 2 < nc) {
                CP16(aDst + st,      Aro + (c + 2) * 32);
                CP16(aDst + st + 16, Aro + (c + 2) * 32 + 8);
                CP16(bDst + st,      Bro + (c + 2) * 32);
                CP16(bDst + st + 16, Bro + (c + 2) * 32 + 8);
            }
            CPCOMMIT();
        }

        // compute chunk c
        {
            const uint32_t sA32 = smb + (uint32_t)(sc * STAGE_BYTES);
            const uint32_t sB32 = sA32 + OP_BYTES;
#pragma unroll
            for (int ks = 0; ks < 2; ks++) {
                const uint32_t kso = (uint32_t)(ks * 32);
                uint32_t b0[4], b1[4];
                ldmx4(b0, sB32 + bOff + kso);                               // n +0..15
                ldmx4(b1, sB32 + bOff + (uint32_t)(16 * PITCHB) + kso);     // n +16..31
#pragma unroll
                for (int i = 0; i < 4; i++) {
                    uint32_t a[4];
                    ldmx4(a, sA32 + aOff + (uint32_t)(i * 16 * PITCHB) + kso);
                    mma_16x8x16(acc[i][0], a, b0);
                    mma_16x8x16(acc[i][1], a, b0 + 2);
                    mma_16x8x16(acc[i][2], a, b1);
                    mma_16x8x16(acc[i][3], a, b1 + 2);
                }
            }
        }
        if (++sc == NSTAGE) sc = 0;
    }

    // ------------------- transposed-V epilogue (QKV GEMM) -------------------
    if (VTR && n0 >= 768) {
        __syncthreads();                    // everyone done with pipeline smem
        __half* ts = (__half*)smem;
#pragma unroll
        for (int i = 0; i < 4; i++) {
            const int r0l = warpM * 64 + i * 16 + g;
            const int r1l = r0l + 8;
#pragma unroll
            for (int j = 0; j < 4; j++) {
                const int cl = warpN * 32 + j * 8 + tg * 2;
                float b0 = BIAS ? bias[n0 + cl]     : 0.0f;
                float b1 = BIAS ? bias[n0 + cl + 1] : 0.0f;
                ts[(cl    ) * VTP + r0l] = __float2half(acc[i][j][0] + b0);
                ts[(cl + 1) * VTP + r0l] = __float2half(acc[i][j][1] + b1);
                ts[(cl    ) * VTP + r1l] = __float2half(acc[i][j][2] + b0);
                ts[(cl + 1) * VTP + r1l] = __float2half(acc[i][j][3] + b1);
            }
        }
        __syncthreads();
        // coalesced out: thread -> (c = tid>>1, 64-half half-row = tid&1)
        const int cR = tid >> 1;
        const int hh = (tid & 1) * 64;
        const int zz = (int)(m0 >> 8);
        const int tb = (int)(m0 & 255);
        __half* vrow = vt + (long)zz * EMB * SEQ
                          + (long)(n0 - 768 + cR) * SEQ + tb + hh;
        const __half* srow = ts + cR * VTP + hh;
#pragma unroll
        for (int u = 0; u < 8; u++)
            *(uint4*)(vrow + u * 8) = *(const uint4*)(srow + u * 8);
        return;
    }

    // ----------------------------- epilogue --------------------------------
    const float* Rz = RESID ? (R + (long)z * sR) : nullptr;
    float*  Cf = (float*)Cv  + (OUTH ? 0 : (long)z * sC);
    __half* Ch = (__half*)Cv + (OUTH ? (long)z * sC : 0);

#pragma unroll
    for (int i = 0; i < 4; i++) {
        const long r0 = m0 + warpM * 64 + i * 16 + g;
        const long r1 = r0 + 8;
#pragma unroll
        for (int j = 0; j < 4; j++) {
            const int cc = n0 + warpN * 32 + j * 8 + tg * 2;
            float2 v0, v1;
            v0.x = acc[i][j][0] * alpha; v0.y = acc[i][j][1] * alpha;
            v1.x = acc[i][j][2] * alpha; v1.y = acc[i][j][3] * alpha;
            if (BIAS) {
                const float2 bv = *(const float2*)(bias + cc);
                v0.x += bv.x; v0.y += bv.y;
                v1.x += bv.x; v1.y += bv.y;
            }
            if (RELU) {
                v0.x = fmaxf(v0.x, 0.0f); v0.y = fmaxf(v0.y, 0.0f);
                v1.x = fmaxf(v1.x, 0.0f); v1.y = fmaxf(v1.y, 0.0f);
            }
            if (RESID) {
                const float2 q0 = *(const float2*)(Rz + r0 * ldc + cc);
                const float2 q1 = *(const float2*)(Rz + r1 * ldc + cc);
                v0.x += q0.x; v0.y += q0.y;
                v1.x += q1.x; v1.y += q1.y;
            }
            if (OUTH) {
                *(__half2*)(Ch + r0 * ldc + cc) = __floats2half2_rn(v0.x, v0.y);
                *(__half2*)(Ch + r1 * ldc + cc) = __floats2half2_rn(v1.x, v1.y);
            } else {
                *(float2*)(Cf + r0 * ldc + cc) = v0;
                *(float2*)(Cf + r1 * ldc + cc) = v1;
            }
        }
    }
}

// ---------------------------------------------------------------------------
// Launch
// ---------------------------------------------------------------------------
extern "C" void kernel_launch(void* const* d_in, const int* /*in_sizes*/, int /*n_in*/,
                              void* d_out, int /*out_size*/)
{
    const float* x      = (const float*)d_in[0];
    const float* W_attn = (const float*)d_in[1];
    const float* b_attn = (const float*)d_in[2];
    const float* W_proj = (const float*)d_in[3];
    const float* b_proj = (const float*)d_in[4];
    const float* ln1_g  = (const float*)d_in[5];
    const float* ln1_b  = (const float*)d_in[6];
    const float* ln2_g  = (const float*)d_in[7];
    const float* ln2_b  = (const float*)d_in[8];
    const float* W1     = (const float*)d_in[9];
    const float* b1     = (const float*)d_in[10];
    const float* W2     = (const float*)d_in[11];
    const float* b2     = (const float*)d_in[12];
    float* out = (float*)d_out;

    __half *h16, *qkv16, *att16, *y16, *f16, *vt16, *wta, *wtp, *w1t, *w2t;
    float *att, *x1;
    cudaGetSymbolAddress((void**)&h16,   g_h16);
    cudaGetSymbolAddress((void**)&qkv16, g_qkv16);
    cudaGetSymbolAddress((void**)&att,   g_att);
    cudaGetSymbolAddress((void**)&att16, g_att16);
    cudaGetSymbolAddress((void**)&y16,   g_y16);
    cudaGetSymbolAddress((void**)&x1,    g_x1);
    cudaGetSymbolAddress((void**)&f16,   g_f16);
    cudaGetSymbolAddress((void**)&vt16,  g_vt16);
    cudaGetSymbolAddress((void**)&wta,   g_wta16);
    cudaGetSymbolAddress((void**)&wtp,   g_wtp16);
    cudaGetSymbolAddress((void**)&w1t,   g_w1t16);
    cudaGetSymbolAddress((void**)&w2t,   g_w2t16);

    cudaFuncSetAttribute(hgemm<true,  false, false, true,  true >,
                         cudaFuncAttributeMaxDynamicSharedMemorySize, SMEM_DYN);
    cudaFuncSetAttribute(hgemm<false, false, false, false, false>,
                         cudaFuncAttributeMaxDynamicSharedMemorySize, SMEM_DYN);
    cudaFuncSetAttribute(hgemm<false, false, false, true,  false>,
                         cudaFuncAttributeMaxDynamicSharedMemorySize, SMEM_DYN);
    cudaFuncSetAttribute(hgemm<true,  false, true,  false, false>,
                         cudaFuncAttributeMaxDynamicSharedMemorySize, SMEM_DYN);
    cudaFuncSetAttribute(hgemm<true,  true,  false, true,  false>,
                         cudaFuncAttributeMaxDynamicSharedMemorySize, SMEM_DYN);

    const float inv_sqrt_c = 0.05103103630798287f;   // 1/sqrt(384)
    const long sQKV = (long)SEQ * (3 * EMB);
    const long sATT = (long)SEQ * SEQ;
    const dim3 tb(32, 8);

    // 0. all weight transposes in one launch (fp32 -> fp16, [K,N] -> [N,K])
    tr_all<<<1728, tb>>>(W_attn, W_proj, W1, W2, wta, wtp, w1t, w2t);

    // 1. h = LN1(x)  (fp16, warp-per-row)
    ln_kernel<<<MROWS / 4, 128>>>(x, ln1_g, ln1_b, h16);

    // 2. qkv = h @ W_attn + b_attn   M=32768, N=1152, K=384  -> fp16
    //    V third (n0>=768) is written TRANSPOSED into vt16 by the epilogue.
    hgemm<true, false, false, true, true><<<dim3(9, 256, 1), 256, SMEM_DYN>>>(
        h16, EMB, 0, wta, EMB, 0, b_attn, nullptr, 0,
        qkv16, 3 * EMB, 0, EMB, 1.0f, 0, vt16);

    // 3. att = q @ k^T / sqrt(C)   M=N=256, K=384  -> fp32 logits
    //    (causal=1: all-masked upper tile skipped, never read)
    hgemm<false, false, false, false, false><<<dim3(2, 2, BATCH), 256, SMEM_DYN>>>(
        qkv16, 3 * EMB, sQKV, qkv16 + EMB, 3 * EMB, sQKV, nullptr, nullptr, 0,
        att, SEQ, sATT, EMB, inv_sqrt_c, 1, nullptr);

    // 4. causal softmax -> fp16 probs (warp-per-row)
    softmax_causal<<<MROWS / 4, 128>>>(att, att16);

    // 5. y = att @ V (via Vt)   M=256, N=384, K=256  -> fp16
    //    (causal=2: rows < 128 only need K=128)
    hgemm<false, false, false, true, false><<<dim3(3, 2, BATCH), 256, SMEM_DYN>>>(
        att16, SEQ, sATT, vt16, SEQ, (long)EMB * SEQ, nullptr, nullptr, 0,
        y16, EMB, (long)SEQ * EMB, SEQ, 1.0f, 2, nullptr);

    // 6. x1 = x + y @ W_proj + b_proj   M=32768, N=384, K=384  -> fp32
    hgemm<true, false, true, false, false><<<dim3(3, 256, 1), 256, SMEM_DYN>>>(
        y16, EMB, 0, wtp, EMB, 0, b_proj, x, 0,
        x1, EMB, 0, EMB, 1.0f, 0, nullptr);

    // 7. h2 = LN2(x1)  (fp16, reuse h16)
    ln_kernel<<<MROWS / 4, 128>>>(x1, ln2_g, ln2_b, h16);

    // 8. f = relu(h2 @ W1 + b1)   M=32768, N=1536, K=384  -> fp16
    hgemm<true, true, false, true, false><<<dim3(12, 256, 1), 256, SMEM_DYN>>>(
        h16, EMB, 0, w1t, EMB, 0, b1, nullptr, 0,
        f16, 4 * EMB, 0, EMB, 1.0f, 0, nullptr);

    // 9. out = x1 + f @ W2 + b2   M=32768, N=384, K=1536  -> fp32
    hgemm<true, false, true, false, false><<<dim3(3, 256, 1), 256, SMEM_DYN>>>(
        f16, 4 * EMB, 0, w2t, 4 * EMB, 0, b2, x1, 0,
        out, EMB, 0, 4 * EMB, 1.0f, 0, nullptr);
}